// round 5
// baseline (speedup 1.0000x reference)
#include <cuda_runtime.h>
#include <math.h>
#include <stdint.h>

#define B_SZ   2
#define LSEQ   1024
#define DM     1024
#define DI     2048
#define DS     16
#define MROWS  (B_SZ * LSEQ)   // 2048

// ---------------------------------------------------------------------------
// Scratch (__device__ globals; no allocations allowed)
// ---------------------------------------------------------------------------
__device__ float g_xz[MROWS * 2 * DI];
__device__ float g_xconv[MROWS * DI];
__device__ float g_delta[MROWS * DI];
__device__ float g_bc[MROWS * 2 * DS];
__device__ float g_yz[MROWS * DI];
__device__ float g_mmout[MROWS * DM];
__device__ float g_xr[MROWS * DM];          // tf32-rounded x
__device__ float g_wt_in[(2 * DI) * DM];    // W_in^T  [4096,1024] (tf32-rounded)
__device__ float g_wt_dt[DI * DI];          // W_dt^T  [2048,2048]
__device__ float g_wt_out[DM * DI];         // W_out^T [1024,2048]

// ---------------------------------------------------------------------------
// helpers
// ---------------------------------------------------------------------------
static __device__ __forceinline__ float tf32r(float f) {
    uint32_t u;
    asm("cvt.rna.tf32.f32 %0, %1;" : "=r"(u) : "f"(f));
    return __uint_as_float(u);
}
static __device__ __forceinline__ uint32_t smem_u32(const void* p) {
    uint32_t a;
    asm("{ .reg .u64 t; cvta.to.shared.u64 t, %1; cvt.u32.u64 %0, t; }"
        : "=r"(a) : "l"(p));
    return a;
}
static __device__ __forceinline__ void cp_async16(uint32_t sa, const void* ga) {
    asm volatile("cp.async.cg.shared.global [%0], [%1], 16;" :: "r"(sa), "l"(ga));
}
static __device__ __forceinline__ void cp_commit() {
    asm volatile("cp.async.commit_group;" ::: "memory");
}
static __device__ __forceinline__ void cp_wait1() {
    asm volatile("cp.async.wait_group 1;" ::: "memory");
}
static __device__ __forceinline__ void mma1688(float* d, const uint32_t* a,
                                               const uint32_t* b) {
    asm volatile(
        "mma.sync.aligned.m16n8k8.row.col.f32.tf32.tf32.f32 "
        "{%0,%1,%2,%3}, {%4,%5,%6,%7}, {%8,%9}, {%0,%1,%2,%3};"
        : "+f"(d[0]), "+f"(d[1]), "+f"(d[2]), "+f"(d[3])
        : "r"(a[0]), "r"(a[1]), "r"(a[2]), "r"(a[3]), "r"(b[0]), "r"(b[1]));
}

// ---------------------------------------------------------------------------
// tf32 mma.sync GEMM: C[M,N] = A[M,K] @ Bt[N,K]^T + bias; EPI=1 -> softplus.
// Block 128x128, BK=32, 3-stage cp.async, 256 thr (8 warps, 2x4), warp 64x32.
// A, Bt must be pre-rounded to tf32. M%128==0, N%128==0, K%32==0.
// ---------------------------------------------------------------------------
#define BM 128
#define BN 128
#define BK 32
#define STRD 36                         // floats per smem row (conflict-free)
#define ATILE (BM * STRD)               // 4608 floats
#define BTILE (BN * STRD)
#define NSTG 3
#define GSMEM ((ATILE + BTILE) * NSTG * 4)   // 110592 bytes

template <int EPI>
__global__ __launch_bounds__(256, 1)
void gemm_mma(const float* __restrict__ A, const float* __restrict__ Bt,
              const float* __restrict__ bias, float* __restrict__ C,
              int M, int N, int K)
{
    extern __shared__ float sm[];
    float* As = sm;                     // [NSTG][BM][STRD]
    float* Bs = sm + NSTG * ATILE;      // [NSTG][BN][STRD]

    const int tid  = threadIdx.x;
    const int lane = tid & 31;
    const int wid  = tid >> 5;
    const int wm   = (wid >> 2) * 64;   // warp m offset
    const int wn   = (wid & 3) * 32;    // warp n offset
    const int bm = blockIdx.y * BM;
    const int bn = blockIdx.x * BN;

    float acc[4][4][4];
#pragma unroll
    for (int mi = 0; mi < 4; mi++)
#pragma unroll
        for (int ni = 0; ni < 4; ni++)
#pragma unroll
            for (int r = 0; r < 4; r++) acc[mi][ni][r] = 0.f;

    auto load_tile = [&](int j) {
        const int stg = j % NSTG;
        const int k0 = j * BK;
        float* ad = As + stg * ATILE;
        float* bd = Bs + stg * BTILE;
#pragma unroll
        for (int q = 0; q < 4; q++) {
            int ch = tid + q * 256;
            int row = ch >> 3, col = ch & 7;
            cp_async16(smem_u32(ad + row * STRD + col * 4),
                       A + (size_t)(bm + row) * K + k0 + col * 4);
        }
#pragma unroll
        for (int q = 0; q < 4; q++) {
            int ch = tid + q * 256;
            int row = ch >> 3, col = ch & 7;
            cp_async16(smem_u32(bd + row * STRD + col * 4),
                       Bt + (size_t)(bn + row) * K + k0 + col * 4);
        }
    };

    const int KT = K / BK;
    load_tile(0);
    cp_commit();
    load_tile(1);
    cp_commit();

    for (int i = 0; i < KT; i++) {
        cp_wait1();                      // tile i resident (<=1 group pending)
        __syncthreads();                 // all warps done reading stage (i-1)%3
        if (i + 2 < KT) load_tile(i + 2);
        cp_commit();                     // (possibly empty group)

        const int stg = i % NSTG;
        const float* ad = As + stg * ATILE;
        const float* bd = Bs + stg * BTILE;

#pragma unroll
        for (int kk = 0; kk < BK; kk += 8) {
            uint32_t af[4][4];
            uint32_t bf[4][2];
#pragma unroll
            for (int mi = 0; mi < 4; mi++) {
                const float* p = ad + (wm + mi * 16 + (lane >> 2)) * STRD
                                 + kk + (lane & 3);
                af[mi][0] = __float_as_uint(p[0]);
                af[mi][1] = __float_as_uint(p[8 * STRD]);
                af[mi][2] = __float_as_uint(p[4]);
                af[mi][3] = __float_as_uint(p[8 * STRD + 4]);
            }
#pragma unroll
            for (int ni = 0; ni < 4; ni++) {
                const float* p = bd + (wn + ni * 8 + (lane >> 2)) * STRD
                                 + kk + (lane & 3);
                bf[ni][0] = __float_as_uint(p[0]);
                bf[ni][1] = __float_as_uint(p[4]);
            }
#pragma unroll
            for (int mi = 0; mi < 4; mi++)
#pragma unroll
                for (int ni = 0; ni < 4; ni++)
                    mma1688(acc[mi][ni], af[mi], bf[ni]);
        }
    }

    // ---- epilogue ---------------------------------------------------------
#pragma unroll
    for (int mi = 0; mi < 4; mi++) {
#pragma unroll
        for (int ni = 0; ni < 4; ni++) {
            int r0 = bm + wm + mi * 16 + (lane >> 2);
            int c0 = bn + wn + ni * 8 + (lane & 3) * 2;
            float2 bv = *(const float2*)(bias + c0);
            float2 v0, v1;
            v0.x = acc[mi][ni][0] + bv.x;
            v0.y = acc[mi][ni][1] + bv.y;
            v1.x = acc[mi][ni][2] + bv.x;
            v1.y = acc[mi][ni][3] + bv.y;
            if (EPI == 1) {
                v0.x = (v0.x > 15.f) ? v0.x : log1pf(__expf(v0.x));
                v0.y = (v0.y > 15.f) ? v0.y : log1pf(__expf(v0.y));
                v1.x = (v1.x > 15.f) ? v1.x : log1pf(__expf(v1.x));
                v1.y = (v1.y > 15.f) ? v1.y : log1pf(__expf(v1.y));
            }
            *(float2*)(C + (size_t)r0 * N + c0) = v0;
            *(float2*)(C + (size_t)(r0 + 8) * N + c0) = v1;
        }
    }
}

// ---------------------------------------------------------------------------
// tf32 rounding copy (for x)
// ---------------------------------------------------------------------------
__global__ __launch_bounds__(256)
void round_copy(const float* __restrict__ in, float* __restrict__ out, int n)
{
    int i = blockIdx.x * 256 + threadIdx.x;
    if (i < n) out[i] = tf32r(in[i]);
}

// ---------------------------------------------------------------------------
// Weight transpose + tf32 rounding: Wt[n,k] = tf32(W[k,n])
// ---------------------------------------------------------------------------
__global__ __launch_bounds__(256)
void transposeW(const float* __restrict__ W, float* __restrict__ Wt, int K, int N)
{
    __shared__ float t[32][33];
    int n0 = blockIdx.x * 32, k0 = blockIdx.y * 32;
    int tx = threadIdx.x & 31, ty = threadIdx.x >> 5;
#pragma unroll
    for (int i = ty; i < 32; i += 8)
        t[i][tx] = W[(size_t)(k0 + i) * N + n0 + tx];
    __syncthreads();
#pragma unroll
    for (int i = ty; i < 32; i += 8)
        Wt[(size_t)(n0 + i) * K + k0 + tx] = tf32r(t[tx][i]);
}

// ---------------------------------------------------------------------------
// Depthwise causal conv (width 4) + SiLU; output tf32-rounded (GEMM2 operand)
// ---------------------------------------------------------------------------
__global__ void conv_silu(const float* __restrict__ cw, const float* __restrict__ cb)
{
    int idx = blockIdx.x * 256 + threadIdx.x;
    if (idx >= MROWS * DI) return;
    int d  = idx & (DI - 1);
    int lm = idx >> 11;
    int l  = lm & (LSEQ - 1);

    const float* xp = g_xz + (size_t)lm * (2 * DI) + d;
    float acc = cb[d];
#pragma unroll
    for (int j = 0; j < 4; j++) {
        int ll = l - 3 + j;
        if (ll >= 0) acc += xp[(j - 3) * (2 * DI)] * cw[d * 4 + j];
    }
    g_xconv[idx] = tf32r(acc / (1.f + __expf(-acc)));
}

// ---------------------------------------------------------------------------
// B,C projection (K=2048, N=32), fp32
// ---------------------------------------------------------------------------
__global__ __launch_bounds__(256)
void proj_bc(const float* __restrict__ W, const float* __restrict__ bias)
{
    __shared__ float Ws[256 * 32];
    int m = blockIdx.x * 8 + (threadIdx.x >> 5);
    int n = threadIdx.x & 31;
    const float* a = g_xconv + (size_t)m * DI;
    float acc = bias[n];
    for (int k0 = 0; k0 < DI; k0 += 256) {
        __syncthreads();
        for (int i = threadIdx.x; i < 256 * 32; i += 256)
            Ws[i] = W[(size_t)k0 * 32 + i];
        __syncthreads();
#pragma unroll 8
        for (int kk = 0; kk < 256; kk++)
            acc += a[k0 + kk] * Ws[kk * 32 + n];
    }
    g_bc[(size_t)m * 32 + n] = acc;
}

// ---------------------------------------------------------------------------
// Selective scan + gate (software-pipelined loads); output tf32-rounded
// ---------------------------------------------------------------------------
__global__ __launch_bounds__(128)
void scan_kernel(const float* __restrict__ A_log, const float* __restrict__ D_skip)
{
    int grp = threadIdx.x >> 4;
    int s   = threadIdx.x & 15;
    int g   = blockIdx.x * 8 + grp;
    int b   = g >> 11;
    int d   = g & (DI - 1);

    float Av = -__expf(A_log[d * DS + s]);
    float Dv = D_skip[d];
    float h  = 0.f;

    const float* dp  = g_delta + (size_t)b * LSEQ * DI + d;
    const float* xp  = g_xconv + (size_t)b * LSEQ * DI + d;
    const float* zp  = g_xz + (size_t)b * LSEQ * (2 * DI) + DI + d;
    const float* bcp = g_bc + (size_t)b * LSEQ * (2 * DS);
    float* yp = g_yz + (size_t)b * LSEQ * DI + d;

    float dv = dp[0];
    float xv = xp[0];
    float Bv = bcp[s];
    float Cv = bcp[16 + s];

    for (int t = 0; t < LSEQ; t++) {
        float dvn = 0.f, xvn = 0.f, Bvn = 0.f, Cvn = 0.f;
        if (t + 1 < LSEQ) {
            dvn = dp[(size_t)(t + 1) * DI];
            xvn = xp[(size_t)(t + 1) * DI];
            Bvn = bcp[(t + 1) * 32 + s];
            Cvn = bcp[(t + 1) * 32 + 16 + s];
        }
        float dA = __expf(dv * Av);
        h = fmaf(dA, h, dv * xv * Bv);
        float p = h * Cv;
        p += __shfl_xor_sync(0xffffffffu, p, 8);
        p += __shfl_xor_sync(0xffffffffu, p, 4);
        p += __shfl_xor_sync(0xffffffffu, p, 2);
        p += __shfl_xor_sync(0xffffffffu, p, 1);
        if (s == 0) {
            float y = p + Dv * xv;
            float z = zp[(size_t)t * (2 * DI)];
            yp[(size_t)t * DI] = tf32r(y * (z / (1.f + __expf(-z))));
        }
        dv = dvn; xv = xvn; Bv = Bvn; Cv = Cvn;
    }
}

// ---------------------------------------------------------------------------
// residual add + LayerNorm (unbiased std, eps added to std)
// ---------------------------------------------------------------------------
__global__ __launch_bounds__(256)
void add_layernorm(const float* __restrict__ res, const float* __restrict__ alpha,
                   const float* __restrict__ beta, float* __restrict__ out)
{
    __shared__ float red[8];
    int row = blockIdx.x;
    int tid = threadIdx.x;

    float loc[4];
    float sgm = 0.f;
#pragma unroll
    for (int j = 0; j < 4; j++) {
        int i = tid + j * 256;
        loc[j] = res[(size_t)row * DM + i] + g_mmout[(size_t)row * DM + i];
        sgm += loc[j];
    }
#pragma unroll
    for (int o = 16; o; o >>= 1) sgm += __shfl_xor_sync(0xffffffffu, sgm, o);
    if ((tid & 31) == 0) red[tid >> 5] = sgm;
    __syncthreads();
    float tot = red[0];
#pragma unroll
    for (int i = 1; i < 8; i++) tot += red[i];
    float mean = tot * (1.f / DM);
    __syncthreads();

    float q = 0.f;
#pragma unroll
    for (int j = 0; j < 4; j++) {
        float df = loc[j] - mean;
        q += df * df;
    }
#pragma unroll
    for (int o = 16; o; o >>= 1) q += __shfl_xor_sync(0xffffffffu, q, o);
    if ((tid & 31) == 0) red[tid >> 5] = q;
    __syncthreads();
    float qt = red[0];
#pragma unroll
    for (int i = 1; i < 8; i++) qt += red[i];

    float stdv = sqrtf(qt * (1.f / (DM - 1)));
    float inv = 1.f / (stdv + 1e-6f);
#pragma unroll
    for (int j = 0; j < 4; j++) {
        int i = tid + j * 256;
        out[(size_t)row * DM + i] = alpha[i] * (loc[j] - mean) * inv + beta[i];
    }
}

// ---------------------------------------------------------------------------
// Launch sequence
// ---------------------------------------------------------------------------
extern "C" void kernel_launch(void* const* d_in, const int* in_sizes, int n_in,
                              void* d_out, int out_size)
{
    const float* x      = (const float*)d_in[0];
    const float* W_in   = (const float*)d_in[1];
    const float* b_in   = (const float*)d_in[2];
    const float* conv_w = (const float*)d_in[3];
    const float* conv_b = (const float*)d_in[4];
    const float* W_xp   = (const float*)d_in[5];
    const float* b_xp   = (const float*)d_in[6];
    const float* W_dt   = (const float*)d_in[7];
    const float* b_dt   = (const float*)d_in[8];
    const float* A_log  = (const float*)d_in[9];
    const float* D_skip = (const float*)d_in[10];
    const float* W_out  = (const float*)d_in[11];
    const float* b_out  = (const float*)d_in[12];
    const float* alpha  = (const float*)d_in[13];
    const float* beta   = (const float*)d_in[14];
    float* out = (float*)d_out;

    float *xz, *xconv, *delta, *yz, *mmout, *xr, *wt_in, *wt_dt, *wt_out;
    cudaGetSymbolAddress((void**)&xz,     g_xz);
    cudaGetSymbolAddress((void**)&xconv,  g_xconv);
    cudaGetSymbolAddress((void**)&delta,  g_delta);
    cudaGetSymbolAddress((void**)&yz,     g_yz);
    cudaGetSymbolAddress((void**)&mmout,  g_mmout);
    cudaGetSymbolAddress((void**)&xr,     g_xr);
    cudaGetSymbolAddress((void**)&wt_in,  g_wt_in);
    cudaGetSymbolAddress((void**)&wt_dt,  g_wt_dt);
    cudaGetSymbolAddress((void**)&wt_out, g_wt_out);

    cudaFuncSetAttribute(gemm_mma<0>, cudaFuncAttributeMaxDynamicSharedMemorySize, GSMEM);
    cudaFuncSetAttribute(gemm_mma<1>, cudaFuncAttributeMaxDynamicSharedMemorySize, GSMEM);

    // operand prep (tf32 rounding)
    round_copy<<<(MROWS * DM + 255) / 256, 256>>>(x, xr, MROWS * DM);
    transposeW<<<dim3((2 * DI) / 32, DM / 32), 256>>>(W_in,  wt_in,  DM, 2 * DI);
    transposeW<<<dim3(DI / 32, DI / 32),        256>>>(W_dt,  wt_dt,  DI, DI);
    transposeW<<<dim3(DM / 32, DI / 32),        256>>>(W_out, wt_out, DI, DM);

    // 1) in-proj: xz = x @ W_in + b_in     (M=2048, N=4096, K=1024)
    gemm_mma<0><<<dim3((2 * DI) / BN, MROWS / BM), 256, GSMEM>>>(
        xr, wt_in, b_in, xz, MROWS, 2 * DI, DM);

    // 2) depthwise causal conv + silu
    conv_silu<<<(MROWS * DI) / 256, 256>>>(conv_w, conv_b);

    // 3) B,C projection
    proj_bc<<<MROWS / 8, 256>>>(W_xp, b_xp);

    // 4) delta = softplus(x_conv @ W_dt + b_dt)  (2048 x 2048 x 2048)
    gemm_mma<1><<<dim3(DI / BN, MROWS / BM), 256, GSMEM>>>(
        xconv, wt_dt, b_dt, delta, MROWS, DI, DI);

    // 5) selective scan + gate
    scan_kernel<<<(B_SZ * DI) / 8, 128>>>(A_log, D_skip);

    // 6) out-proj                                (2048 x 1024 x 2048)
    gemm_mma<0><<<dim3(DM / BN, MROWS / BM), 256, GSMEM>>>(
        yz, wt_out, b_out, mmout, MROWS, DM, DI);

    // 7) residual + layernorm
    add_layernorm<<<MROWS, 256>>>(x, alpha, beta, out);
}

// round 6
// speedup vs baseline: 1.2113x; 1.2113x over previous
#include <cuda_runtime.h>
#include <cuda_fp16.h>
#include <math.h>
#include <stdint.h>

#define B_SZ   2
#define LSEQ   1024
#define DM     1024
#define DI     2048
#define DS     16
#define MROWS  (B_SZ * LSEQ)   // 2048

// ---------------------------------------------------------------------------
// Scratch (__device__ globals; no allocations allowed)
// ---------------------------------------------------------------------------
__device__ float  g_xz[MROWS * 2 * DI];
__device__ float  g_xconv[MROWS * DI];
__device__ float  g_delta[MROWS * DI];
__device__ float  g_bc[MROWS * 2 * DS];
__device__ float  g_mmout[MROWS * DM];
__device__ __half g_xh[MROWS * DM];          // half x          (GEMM1 A)
__device__ __half g_xconvh[MROWS * DI];      // half conv out   (GEMM2 A)
__device__ __half g_yzh[MROWS * DI];         // half scan out   (GEMM3 A)
__device__ __half g_wt_in[(2 * DI) * DM];    // W_in^T  half
__device__ __half g_wt_dt[DI * DI];          // W_dt^T  half
__device__ __half g_wt_out[DM * DI];         // W_out^T half

// ---------------------------------------------------------------------------
// helpers
// ---------------------------------------------------------------------------
static __device__ __forceinline__ uint32_t smem_u32(const void* p) {
    uint32_t a;
    asm("{ .reg .u64 t; cvta.to.shared.u64 t, %1; cvt.u32.u64 %0, t; }"
        : "=r"(a) : "l"(p));
    return a;
}
static __device__ __forceinline__ void cp_async16(uint32_t sa, const void* ga) {
    asm volatile("cp.async.cg.shared.global [%0], [%1], 16;" :: "r"(sa), "l"(ga));
}
static __device__ __forceinline__ void cp_commit() {
    asm volatile("cp.async.commit_group;" ::: "memory");
}
static __device__ __forceinline__ void cp_wait2() {
    asm volatile("cp.async.wait_group 2;" ::: "memory");
}
static __device__ __forceinline__ void mma16816(float* d, const uint32_t* a,
                                                const uint32_t* b) {
    asm volatile(
        "mma.sync.aligned.m16n8k16.row.col.f32.f16.f16.f32 "
        "{%0,%1,%2,%3}, {%4,%5,%6,%7}, {%8,%9}, {%0,%1,%2,%3};"
        : "+f"(d[0]), "+f"(d[1]), "+f"(d[2]), "+f"(d[3])
        : "r"(a[0]), "r"(a[1]), "r"(a[2]), "r"(a[3]), "r"(b[0]), "r"(b[1]));
}

// ---------------------------------------------------------------------------
// fp16 mma.sync GEMM: C[M,N] = A[M,K] @ Bt[N,K]^T + bias (fp32 accum/output).
// EPI=1 -> softplus. Block 128x128, BK=32, 4-stage cp.async, 256 threads
// (8 warps 2x4, warp tile 64x32). M%128==0, N%128==0, K%32==0.
// ---------------------------------------------------------------------------
#define BM 128
#define BN 128
#define BK 32
#define STRDH 40                        // halves per smem row (conflict-free)
#define ATILEH (BM * STRDH)             // 5120 halves
#define BTILEH (BN * STRDH)
#define NSTG 4
#define GSMEM ((ATILEH + BTILEH) * NSTG * 2)   // 81920 bytes

template <int EPI>
__global__ __launch_bounds__(256, 2)
void gemm_mma(const __half* __restrict__ A, const __half* __restrict__ Bt,
              const float* __restrict__ bias, float* __restrict__ C,
              int M, int N, int K)
{
    extern __shared__ __half smh[];
    __half* As = smh;                    // [NSTG][BM][STRDH]
    __half* Bs = smh + NSTG * ATILEH;    // [NSTG][BN][STRDH]

    const int tid  = threadIdx.x;
    const int lane = tid & 31;
    const int wid  = tid >> 5;
    const int wm   = (wid >> 2) * 64;    // warp m offset
    const int wn   = (wid & 3) * 32;     // warp n offset
    const int bm = blockIdx.y * BM;
    const int bn = blockIdx.x * BN;

    float acc[4][4][4];
#pragma unroll
    for (int mi = 0; mi < 4; mi++)
#pragma unroll
        for (int ni = 0; ni < 4; ni++)
#pragma unroll
            for (int r = 0; r < 4; r++) acc[mi][ni][r] = 0.f;

    auto load_tile = [&](int j) {
        const int stg = j % NSTG;
        const int k0 = j * BK;
        __half* ad = As + stg * ATILEH;
        __half* bd = Bs + stg * BTILEH;
#pragma unroll
        for (int q = 0; q < 2; q++) {    // A: 128 rows x 4 chunks(16B)
            int ch = tid + q * 256;
            int row = ch >> 2, col = ch & 3;
            cp_async16(smem_u32(ad + row * STRDH + col * 8),
                       A + (size_t)(bm + row) * K + k0 + col * 8);
        }
#pragma unroll
        for (int q = 0; q < 2; q++) {    // B: 128 rows x 4 chunks(16B)
            int ch = tid + q * 256;
            int row = ch >> 2, col = ch & 3;
            cp_async16(smem_u32(bd + row * STRDH + col * 8),
                       Bt + (size_t)(bn + row) * K + k0 + col * 8);
        }
    };

    const int KT = K / BK;
    load_tile(0); cp_commit();
    load_tile(1); cp_commit();
    load_tile(2); cp_commit();

    for (int i = 0; i < KT; i++) {
        cp_wait2();                      // tile i resident (<=2 groups pending)
        __syncthreads();                 // all warps done with stage (i+3)%4
        if (i + 3 < KT) load_tile(i + 3);
        cp_commit();

        const int stg = i % NSTG;
        const __half* ad = As + stg * ATILEH;
        const __half* bd = Bs + stg * BTILEH;

#pragma unroll
        for (int kk = 0; kk < BK; kk += 16) {
            uint32_t af[4][4];
            uint32_t bf[4][2];
#pragma unroll
            for (int mi = 0; mi < 4; mi++) {
                const __half* p = ad + (wm + mi * 16 + (lane >> 2)) * STRDH
                                  + kk + (lane & 3) * 2;
                af[mi][0] = *(const uint32_t*)(p);
                af[mi][1] = *(const uint32_t*)(p + 8 * STRDH);
                af[mi][2] = *(const uint32_t*)(p + 8);
                af[mi][3] = *(const uint32_t*)(p + 8 * STRDH + 8);
            }
#pragma unroll
            for (int ni = 0; ni < 4; ni++) {
                const __half* p = bd + (wn + ni * 8 + (lane >> 2)) * STRDH
                                  + kk + (lane & 3) * 2;
                bf[ni][0] = *(const uint32_t*)(p);
                bf[ni][1] = *(const uint32_t*)(p + 8);
            }
#pragma unroll
            for (int mi = 0; mi < 4; mi++)
#pragma unroll
                for (int ni = 0; ni < 4; ni++)
                    mma16816(acc[mi][ni], af[mi], bf[ni]);
        }
    }

    // ---- epilogue ---------------------------------------------------------
#pragma unroll
    for (int mi = 0; mi < 4; mi++) {
#pragma unroll
        for (int ni = 0; ni < 4; ni++) {
            int r0 = bm + wm + mi * 16 + (lane >> 2);
            int c0 = bn + wn + ni * 8 + (lane & 3) * 2;
            float2 bv = *(const float2*)(bias + c0);
            float2 v0, v1;
            v0.x = acc[mi][ni][0] + bv.x;
            v0.y = acc[mi][ni][1] + bv.y;
            v1.x = acc[mi][ni][2] + bv.x;
            v1.y = acc[mi][ni][3] + bv.y;
            if (EPI == 1) {
                v0.x = (v0.x > 15.f) ? v0.x : log1pf(__expf(v0.x));
                v0.y = (v0.y > 15.f) ? v0.y : log1pf(__expf(v0.y));
                v1.x = (v1.x > 15.f) ? v1.x : log1pf(__expf(v1.x));
                v1.y = (v1.y > 15.f) ? v1.y : log1pf(__expf(v1.y));
            }
            *(float2*)(C + (size_t)r0 * N + c0) = v0;
            *(float2*)(C + (size_t)(r0 + 8) * N + c0) = v1;
        }
    }
}

// ---------------------------------------------------------------------------
// fp32 -> fp16 copy (for x)
// ---------------------------------------------------------------------------
__global__ __launch_bounds__(256)
void to_half(const float* __restrict__ in, __half* __restrict__ out, int n)
{
    int i = blockIdx.x * 256 + threadIdx.x;
    if (i < n) out[i] = __float2half(in[i]);
}

// ---------------------------------------------------------------------------
// Weight transpose to half: Wt[n,k] = half(W[k,n])
// ---------------------------------------------------------------------------
__global__ __launch_bounds__(256)
void transposeW(const float* __restrict__ W, __half* __restrict__ Wt, int K, int N)
{
    __shared__ float t[32][33];
    int n0 = blockIdx.x * 32, k0 = blockIdx.y * 32;
    int tx = threadIdx.x & 31, ty = threadIdx.x >> 5;
#pragma unroll
    for (int i = ty; i < 32; i += 8)
        t[i][tx] = W[(size_t)(k0 + i) * N + n0 + tx];
    __syncthreads();
#pragma unroll
    for (int i = ty; i < 32; i += 8)
        Wt[(size_t)(n0 + i) * K + k0 + tx] = __float2half(t[tx][i]);
}

// ---------------------------------------------------------------------------
// Depthwise causal conv (width 4) + SiLU; writes fp32 (scan/proj) + half (GEMM2)
// ---------------------------------------------------------------------------
__global__ void conv_silu(const float* __restrict__ cw, const float* __restrict__ cb)
{
    int idx = blockIdx.x * 256 + threadIdx.x;
    if (idx >= MROWS * DI) return;
    int d  = idx & (DI - 1);
    int lm = idx >> 11;
    int l  = lm & (LSEQ - 1);

    const float* xp = g_xz + (size_t)lm * (2 * DI) + d;
    float acc = cb[d];
#pragma unroll
    for (int j = 0; j < 4; j++) {
        int ll = l - 3 + j;
        if (ll >= 0) acc += xp[(j - 3) * (2 * DI)] * cw[d * 4 + j];
    }
    float v = acc / (1.f + __expf(-acc));
    g_xconv[idx]  = v;
    g_xconvh[idx] = __float2half(v);
}

// ---------------------------------------------------------------------------
// B,C projection (K=2048, N=32), fp32
// ---------------------------------------------------------------------------
__global__ __launch_bounds__(256)
void proj_bc(const float* __restrict__ W, const float* __restrict__ bias)
{
    __shared__ float Ws[256 * 32];
    int m = blockIdx.x * 8 + (threadIdx.x >> 5);
    int n = threadIdx.x & 31;
    const float* a = g_xconv + (size_t)m * DI;
    float acc = bias[n];
    for (int k0 = 0; k0 < DI; k0 += 256) {
        __syncthreads();
        for (int i = threadIdx.x; i < 256 * 32; i += 256)
            Ws[i] = W[(size_t)k0 * 32 + i];
        __syncthreads();
#pragma unroll 8
        for (int kk = 0; kk < 256; kk++)
            acc += a[k0 + kk] * Ws[kk * 32 + n];
    }
    g_bc[(size_t)m * 32 + n] = acc;
}

// ---------------------------------------------------------------------------
// Selective scan + gate (software-pipelined loads); output half (GEMM3 A)
// ---------------------------------------------------------------------------
__global__ __launch_bounds__(128)
void scan_kernel(const float* __restrict__ A_log, const float* __restrict__ D_skip)
{
    int grp = threadIdx.x >> 4;
    int s   = threadIdx.x & 15;
    int g   = blockIdx.x * 8 + grp;
    int b   = g >> 11;
    int d   = g & (DI - 1);

    float Av = -__expf(A_log[d * DS + s]);
    float Dv = D_skip[d];
    float h  = 0.f;

    const float* dp  = g_delta + (size_t)b * LSEQ * DI + d;
    const float* xp  = g_xconv + (size_t)b * LSEQ * DI + d;
    const float* zp  = g_xz + (size_t)b * LSEQ * (2 * DI) + DI + d;
    const float* bcp = g_bc + (size_t)b * LSEQ * (2 * DS);
    __half* yp = g_yzh + (size_t)b * LSEQ * DI + d;

    float dv = dp[0];
    float xv = xp[0];
    float Bv = bcp[s];
    float Cv = bcp[16 + s];

    for (int t = 0; t < LSEQ; t++) {
        float dvn = 0.f, xvn = 0.f, Bvn = 0.f, Cvn = 0.f;
        if (t + 1 < LSEQ) {
            dvn = dp[(size_t)(t + 1) * DI];
            xvn = xp[(size_t)(t + 1) * DI];
            Bvn = bcp[(t + 1) * 32 + s];
            Cvn = bcp[(t + 1) * 32 + 16 + s];
        }
        float dA = __expf(dv * Av);
        h = fmaf(dA, h, dv * xv * Bv);
        float p = h * Cv;
        p += __shfl_xor_sync(0xffffffffu, p, 8);
        p += __shfl_xor_sync(0xffffffffu, p, 4);
        p += __shfl_xor_sync(0xffffffffu, p, 2);
        p += __shfl_xor_sync(0xffffffffu, p, 1);
        if (s == 0) {
            float y = p + Dv * xv;
            float z = zp[(size_t)t * (2 * DI)];
            yp[(size_t)t * DI] = __float2half(y * (z / (1.f + __expf(-z))));
        }
        dv = dvn; xv = xvn; Bv = Bvn; Cv = Cvn;
    }
}

// ---------------------------------------------------------------------------
// residual add + LayerNorm (unbiased std, eps added to std)
// ---------------------------------------------------------------------------
__global__ __launch_bounds__(256)
void add_layernorm(const float* __restrict__ res, const float* __restrict__ alpha,
                   const float* __restrict__ beta, float* __restrict__ out)
{
    __shared__ float red[8];
    int row = blockIdx.x;
    int tid = threadIdx.x;

    float loc[4];
    float sgm = 0.f;
#pragma unroll
    for (int j = 0; j < 4; j++) {
        int i = tid + j * 256;
        loc[j] = res[(size_t)row * DM + i] + g_mmout[(size_t)row * DM + i];
        sgm += loc[j];
    }
#pragma unroll
    for (int o = 16; o; o >>= 1) sgm += __shfl_xor_sync(0xffffffffu, sgm, o);
    if ((tid & 31) == 0) red[tid >> 5] = sgm;
    __syncthreads();
    float tot = red[0];
#pragma unroll
    for (int i = 1; i < 8; i++) tot += red[i];
    float mean = tot * (1.f / DM);
    __syncthreads();

    float q = 0.f;
#pragma unroll
    for (int j = 0; j < 4; j++) {
        float df = loc[j] - mean;
        q += df * df;
    }
#pragma unroll
    for (int o = 16; o; o >>= 1) q += __shfl_xor_sync(0xffffffffu, q, o);
    if ((tid & 31) == 0) red[tid >> 5] = q;
    __syncthreads();
    float qt = red[0];
#pragma unroll
    for (int i = 1; i < 8; i++) qt += red[i];

    float stdv = sqrtf(qt * (1.f / (DM - 1)));
    float inv = 1.f / (stdv + 1e-6f);
#pragma unroll
    for (int j = 0; j < 4; j++) {
        int i = tid + j * 256;
        out[(size_t)row * DM + i] = alpha[i] * (loc[j] - mean) * inv + beta[i];
    }
}

// ---------------------------------------------------------------------------
// Launch sequence
// ---------------------------------------------------------------------------
extern "C" void kernel_launch(void* const* d_in, const int* in_sizes, int n_in,
                              void* d_out, int out_size)
{
    const float* x      = (const float*)d_in[0];
    const float* W_in   = (const float*)d_in[1];
    const float* b_in   = (const float*)d_in[2];
    const float* conv_w = (const float*)d_in[3];
    const float* conv_b = (const float*)d_in[4];
    const float* W_xp   = (const float*)d_in[5];
    const float* b_xp   = (const float*)d_in[6];
    const float* W_dt   = (const float*)d_in[7];
    const float* b_dt   = (const float*)d_in[8];
    const float* A_log  = (const float*)d_in[9];
    const float* D_skip = (const float*)d_in[10];
    const float* W_out  = (const float*)d_in[11];
    const float* b_out  = (const float*)d_in[12];
    const float* alpha  = (const float*)d_in[13];
    const float* beta   = (const float*)d_in[14];
    float* out = (float*)d_out;

    float *xz, *delta, *mmout;
    __half *xh, *xconvh, *yzh, *wt_in, *wt_dt, *wt_out;
    cudaGetSymbolAddress((void**)&xz,     g_xz);
    cudaGetSymbolAddress((void**)&delta,  g_delta);
    cudaGetSymbolAddress((void**)&mmout,  g_mmout);
    cudaGetSymbolAddress((void**)&xh,     g_xh);
    cudaGetSymbolAddress((void**)&xconvh, g_xconvh);
    cudaGetSymbolAddress((void**)&yzh,    g_yzh);
    cudaGetSymbolAddress((void**)&wt_in,  g_wt_in);
    cudaGetSymbolAddress((void**)&wt_dt,  g_wt_dt);
    cudaGetSymbolAddress((void**)&wt_out, g_wt_out);

    cudaFuncSetAttribute(gemm_mma<0>, cudaFuncAttributeMaxDynamicSharedMemorySize, GSMEM);
    cudaFuncSetAttribute(gemm_mma<1>, cudaFuncAttributeMaxDynamicSharedMemorySize, GSMEM);

    // operand prep (half conversion)
    to_half<<<(MROWS * DM + 255) / 256, 256>>>(x, xh, MROWS * DM);
    transposeW<<<dim3((2 * DI) / 32, DM / 32), 256>>>(W_in,  wt_in,  DM, 2 * DI);
    transposeW<<<dim3(DI / 32, DI / 32),        256>>>(W_dt,  wt_dt,  DI, DI);
    transposeW<<<dim3(DM / 32, DI / 32),        256>>>(W_out, wt_out, DI, DM);

    // 1) in-proj: xz = x @ W_in + b_in     (M=2048, N=4096, K=1024)
    gemm_mma<0><<<dim3((2 * DI) / BN, MROWS / BM), 256, GSMEM>>>(
        xh, wt_in, b_in, xz, MROWS, 2 * DI, DM);

    // 2) depthwise causal conv + silu
    conv_silu<<<(MROWS * DI) / 256, 256>>>(conv_w, conv_b);

    // 3) B,C projection
    proj_bc<<<MROWS / 8, 256>>>(W_xp, b_xp);

    // 4) delta = softplus(x_conv @ W_dt + b_dt)  (2048 x 2048 x 2048)
    gemm_mma<1><<<dim3(DI / BN, MROWS / BM), 256, GSMEM>>>(
        xconvh, wt_dt, b_dt, delta, MROWS, DI, DI);

    // 5) selective scan + gate
    scan_kernel<<<(B_SZ * DI) / 8, 128>>>(A_log, D_skip);

    // 6) out-proj                                (2048 x 1024 x 2048)
    gemm_mma<0><<<dim3(DM / BN, MROWS / BM), 256, GSMEM>>>(
        yzh, wt_out, b_out, mmout, MROWS, DM, DI);

    // 7) residual + layernorm
    add_layernorm<<<MROWS, 256>>>(x, alpha, beta, out);
}

// round 7
// speedup vs baseline: 1.8780x; 1.5505x over previous
#include <cuda_runtime.h>
#include <cuda_fp16.h>
#include <math.h>
#include <stdint.h>

#define B_SZ   2
#define LSEQ   1024
#define DM     1024
#define DI     2048
#define DS     16
#define MROWS  (B_SZ * LSEQ)   // 2048
#define NCHUNK 16
#define CLEN   (LSEQ / NCHUNK) // 64

// ---------------------------------------------------------------------------
// Scratch (__device__ globals; no allocations allowed)
// ---------------------------------------------------------------------------
__device__ float  g_xz[MROWS * 2 * DI];
__device__ float  g_xconv[MROWS * DI];
__device__ float  g_delta[MROWS * DI];
__device__ float  g_bc[MROWS * 2 * DS];
__device__ float  g_mmout[MROWS * DM];
__device__ __half g_xh[MROWS * DM];          // half x          (GEMM1 A)
__device__ __half g_xconvh[MROWS * DI];      // half conv out   (GEMM2 A)
__device__ __half g_yzh[MROWS * DI];         // half scan out   (GEMM3 A)
__device__ __half g_wt_in[(2 * DI) * DM];    // W_in^T  half
__device__ __half g_wt_dt[DI * DI];          // W_dt^T  half
__device__ __half g_wt_out[DM * DI];         // W_out^T half
// chunked-scan intermediates
__device__ float  g_E[B_SZ * DI * NCHUNK * DS];   // chunk end-state (h0=0)
__device__ float  g_S[B_SZ * DI * NCHUNK];        // chunk sum(delta)
__device__ float  g_Hi[B_SZ * DI * NCHUNK * DS];  // chunk true init state

// ---------------------------------------------------------------------------
// helpers
// ---------------------------------------------------------------------------
static __device__ __forceinline__ uint32_t smem_u32(const void* p) {
    uint32_t a;
    asm("{ .reg .u64 t; cvta.to.shared.u64 t, %1; cvt.u32.u64 %0, t; }"
        : "=r"(a) : "l"(p));
    return a;
}
static __device__ __forceinline__ void cp_async16(uint32_t sa, const void* ga) {
    asm volatile("cp.async.cg.shared.global [%0], [%1], 16;" :: "r"(sa), "l"(ga));
}
static __device__ __forceinline__ void cp_commit() {
    asm volatile("cp.async.commit_group;" ::: "memory");
}
static __device__ __forceinline__ void cp_wait2() {
    asm volatile("cp.async.wait_group 2;" ::: "memory");
}
static __device__ __forceinline__ void mma16816(float* d, const uint32_t* a,
                                                const uint32_t* b) {
    asm volatile(
        "mma.sync.aligned.m16n8k16.row.col.f32.f16.f16.f32 "
        "{%0,%1,%2,%3}, {%4,%5,%6,%7}, {%8,%9}, {%0,%1,%2,%3};"
        : "+f"(d[0]), "+f"(d[1]), "+f"(d[2]), "+f"(d[3])
        : "r"(a[0]), "r"(a[1]), "r"(a[2]), "r"(a[3]), "r"(b[0]), "r"(b[1]));
}

// ---------------------------------------------------------------------------
// fp16 mma.sync GEMM (fp32 accum). EPI=1 -> softplus. 128x128x32 tiles,
// 4-stage cp.async, 256 threads (8 warps 2x4, warp 64x32).
// ---------------------------------------------------------------------------
#define BM 128
#define BN 128
#define BK 32
#define STRDH 40
#define ATILEH (BM * STRDH)
#define BTILEH (BN * STRDH)
#define NSTG 4
#define GSMEM ((ATILEH + BTILEH) * NSTG * 2)   // 81920 bytes

template <int EPI>
__global__ __launch_bounds__(256, 2)
void gemm_mma(const __half* __restrict__ A, const __half* __restrict__ Bt,
              const float* __restrict__ bias, float* __restrict__ C,
              int M, int N, int K)
{
    extern __shared__ __half smh[];
    __half* As = smh;
    __half* Bs = smh + NSTG * ATILEH;

    const int tid  = threadIdx.x;
    const int lane = tid & 31;
    const int wid  = tid >> 5;
    const int wm   = (wid >> 2) * 64;
    const int wn   = (wid & 3) * 32;
    const int bm = blockIdx.y * BM;
    const int bn = blockIdx.x * BN;

    float acc[4][4][4];
#pragma unroll
    for (int mi = 0; mi < 4; mi++)
#pragma unroll
        for (int ni = 0; ni < 4; ni++)
#pragma unroll
            for (int r = 0; r < 4; r++) acc[mi][ni][r] = 0.f;

    auto load_tile = [&](int j) {
        const int stg = j % NSTG;
        const int k0 = j * BK;
        __half* ad = As + stg * ATILEH;
        __half* bd = Bs + stg * BTILEH;
#pragma unroll
        for (int q = 0; q < 2; q++) {
            int ch = tid + q * 256;
            int row = ch >> 2, col = ch & 3;
            cp_async16(smem_u32(ad + row * STRDH + col * 8),
                       A + (size_t)(bm + row) * K + k0 + col * 8);
        }
#pragma unroll
        for (int q = 0; q < 2; q++) {
            int ch = tid + q * 256;
            int row = ch >> 2, col = ch & 3;
            cp_async16(smem_u32(bd + row * STRDH + col * 8),
                       Bt + (size_t)(bn + row) * K + k0 + col * 8);
        }
    };

    const int KT = K / BK;
    load_tile(0); cp_commit();
    load_tile(1); cp_commit();
    load_tile(2); cp_commit();

    for (int i = 0; i < KT; i++) {
        cp_wait2();
        __syncthreads();
        if (i + 3 < KT) load_tile(i + 3);
        cp_commit();

        const int stg = i % NSTG;
        const __half* ad = As + stg * ATILEH;
        const __half* bd = Bs + stg * BTILEH;

#pragma unroll
        for (int kk = 0; kk < BK; kk += 16) {
            uint32_t af[4][4];
            uint32_t bf[4][2];
#pragma unroll
            for (int mi = 0; mi < 4; mi++) {
                const __half* p = ad + (wm + mi * 16 + (lane >> 2)) * STRDH
                                  + kk + (lane & 3) * 2;
                af[mi][0] = *(const uint32_t*)(p);
                af[mi][1] = *(const uint32_t*)(p + 8 * STRDH);
                af[mi][2] = *(const uint32_t*)(p + 8);
                af[mi][3] = *(const uint32_t*)(p + 8 * STRDH + 8);
            }
#pragma unroll
            for (int ni = 0; ni < 4; ni++) {
                const __half* p = bd + (wn + ni * 8 + (lane >> 2)) * STRDH
                                  + kk + (lane & 3) * 2;
                bf[ni][0] = *(const uint32_t*)(p);
                bf[ni][1] = *(const uint32_t*)(p + 8);
            }
#pragma unroll
            for (int mi = 0; mi < 4; mi++)
#pragma unroll
                for (int ni = 0; ni < 4; ni++)
                    mma16816(acc[mi][ni], af[mi], bf[ni]);
        }
    }

#pragma unroll
    for (int mi = 0; mi < 4; mi++) {
#pragma unroll
        for (int ni = 0; ni < 4; ni++) {
            int r0 = bm + wm + mi * 16 + (lane >> 2);
            int c0 = bn + wn + ni * 8 + (lane & 3) * 2;
            float2 bv = *(const float2*)(bias + c0);
            float2 v0, v1;
            v0.x = acc[mi][ni][0] + bv.x;
            v0.y = acc[mi][ni][1] + bv.y;
            v1.x = acc[mi][ni][2] + bv.x;
            v1.y = acc[mi][ni][3] + bv.y;
            if (EPI == 1) {
                v0.x = (v0.x > 15.f) ? v0.x : log1pf(__expf(v0.x));
                v0.y = (v0.y > 15.f) ? v0.y : log1pf(__expf(v0.y));
                v1.x = (v1.x > 15.f) ? v1.x : log1pf(__expf(v1.x));
                v1.y = (v1.y > 15.f) ? v1.y : log1pf(__expf(v1.y));
            }
            *(float2*)(C + (size_t)r0 * N + c0) = v0;
            *(float2*)(C + (size_t)(r0 + 8) * N + c0) = v1;
        }
    }
}

// ---------------------------------------------------------------------------
// fp32 -> fp16 copy (for x)
// ---------------------------------------------------------------------------
__global__ __launch_bounds__(256)
void to_half(const float* __restrict__ in, __half* __restrict__ out, int n)
{
    int i = blockIdx.x * 256 + threadIdx.x;
    if (i < n) out[i] = __float2half(in[i]);
}

// ---------------------------------------------------------------------------
// Weight transpose to half: Wt[n,k] = half(W[k,n])
// ---------------------------------------------------------------------------
__global__ __launch_bounds__(256)
void transposeW(const float* __restrict__ W, __half* __restrict__ Wt, int K, int N)
{
    __shared__ float t[32][33];
    int n0 = blockIdx.x * 32, k0 = blockIdx.y * 32;
    int tx = threadIdx.x & 31, ty = threadIdx.x >> 5;
#pragma unroll
    for (int i = ty; i < 32; i += 8)
        t[i][tx] = W[(size_t)(k0 + i) * N + n0 + tx];
    __syncthreads();
#pragma unroll
    for (int i = ty; i < 32; i += 8)
        Wt[(size_t)(n0 + i) * K + k0 + tx] = __float2half(t[tx][i]);
}

// ---------------------------------------------------------------------------
// Depthwise causal conv (width 4) + SiLU; fp32 + half outputs
// ---------------------------------------------------------------------------
__global__ void conv_silu(const float* __restrict__ cw, const float* __restrict__ cb)
{
    int idx = blockIdx.x * 256 + threadIdx.x;
    if (idx >= MROWS * DI) return;
    int d  = idx & (DI - 1);
    int lm = idx >> 11;
    int l  = lm & (LSEQ - 1);

    const float* xp = g_xz + (size_t)lm * (2 * DI) + d;
    float acc = cb[d];
#pragma unroll
    for (int j = 0; j < 4; j++) {
        int ll = l - 3 + j;
        if (ll >= 0) acc += xp[(j - 3) * (2 * DI)] * cw[d * 4 + j];
    }
    float v = acc / (1.f + __expf(-acc));
    g_xconv[idx]  = v;
    g_xconvh[idx] = __float2half(v);
}

// ---------------------------------------------------------------------------
// B,C projection (K=2048, N=32), fp32
// ---------------------------------------------------------------------------
__global__ __launch_bounds__(256)
void proj_bc(const float* __restrict__ W, const float* __restrict__ bias)
{
    __shared__ float Ws[256 * 32];
    int m = blockIdx.x * 8 + (threadIdx.x >> 5);
    int n = threadIdx.x & 31;
    const float* a = g_xconv + (size_t)m * DI;
    float acc = bias[n];
    for (int k0 = 0; k0 < DI; k0 += 256) {
        __syncthreads();
        for (int i = threadIdx.x; i < 256 * 32; i += 256)
            Ws[i] = W[(size_t)k0 * 32 + i];
        __syncthreads();
#pragma unroll 8
        for (int kk = 0; kk < 256; kk++)
            acc += a[k0 + kk] * Ws[kk * 32 + n];
    }
    g_bc[(size_t)m * 32 + n] = acc;
}

// ---------------------------------------------------------------------------
// Chunked selective scan.
// Pass 1: per (b,d,chunk,s): h-scan from 0 over CLEN steps; also sum(delta).
// ---------------------------------------------------------------------------
__global__ __launch_bounds__(128)
void scan_pass1(const float* __restrict__ A_log)
{
    int grp = threadIdx.x >> 4;
    int s   = threadIdx.x & 15;
    int gid = blockIdx.x * 8 + grp;          // (bd, chunk)
    int chunk = gid & (NCHUNK - 1);
    int bd  = gid >> 4;                      // b*DI + d
    int b   = bd >> 11;
    int d   = bd & (DI - 1);

    float Av = -__expf(A_log[d * DS + s]);
    const size_t base = ((size_t)b * LSEQ + chunk * CLEN) * DI + d;
    const float* dp  = g_delta + base;
    const float* xp  = g_xconv + base;
    const float* bcp = g_bc + ((size_t)b * LSEQ + chunk * CLEN) * (2 * DS);

    float h = 0.f, S = 0.f;
    for (int t = 0; t < CLEN; t++) {
        float dv = dp[(size_t)t * DI];
        float xv = xp[(size_t)t * DI];
        float Bv = bcp[t * 32 + s];
        h = fmaf(__expf(dv * Av), h, dv * xv * Bv);
        S += dv;
    }
    g_E[gid * DS + s] = h;
    if (s == 0) g_S[gid] = S;
}

// Combine: per (b,d,s): serial prefix over 16 chunks -> true initial states.
__global__ __launch_bounds__(256)
void scan_combine(const float* __restrict__ A_log)
{
    int idx = blockIdx.x * 256 + threadIdx.x;   // (bd, s)
    int s  = idx & 15;
    int bd = idx >> 4;
    int d  = bd & (DI - 1);
    float Av = -__expf(A_log[d * DS + s]);
    float H = 0.f;
#pragma unroll
    for (int c = 0; c < NCHUNK; c++) {
        int gid = bd * NCHUNK + c;
        g_Hi[gid * DS + s] = H;
        H = fmaf(__expf(Av * g_S[gid]), H, g_E[gid * DS + s]);
    }
}

// Pass 2: re-scan each chunk from its true init state; emit y*silu(z) as half.
__global__ __launch_bounds__(128)
void scan_pass2(const float* __restrict__ A_log, const float* __restrict__ D_skip)
{
    int grp = threadIdx.x >> 4;
    int s   = threadIdx.x & 15;
    int gid = blockIdx.x * 8 + grp;
    int chunk = gid & (NCHUNK - 1);
    int bd  = gid >> 4;
    int b   = bd >> 11;
    int d   = bd & (DI - 1);

    float Av = -__expf(A_log[d * DS + s]);
    float Dv = D_skip[d];
    const size_t base = ((size_t)b * LSEQ + chunk * CLEN) * DI + d;
    const float* dp  = g_delta + base;
    const float* xp  = g_xconv + base;
    const float* zp  = g_xz + ((size_t)b * LSEQ + chunk * CLEN) * (2 * DI) + DI + d;
    const float* bcp = g_bc + ((size_t)b * LSEQ + chunk * CLEN) * (2 * DS);
    __half* yp = g_yzh + base;

    float h = g_Hi[gid * DS + s];
    for (int t = 0; t < CLEN; t++) {
        float dv = dp[(size_t)t * DI];
        float xv = xp[(size_t)t * DI];
        float Bv = bcp[t * 32 + s];
        float Cv = bcp[t * 32 + 16 + s];
        h = fmaf(__expf(dv * Av), h, dv * xv * Bv);
        float p = h * Cv;
        p += __shfl_xor_sync(0xffffffffu, p, 8);
        p += __shfl_xor_sync(0xffffffffu, p, 4);
        p += __shfl_xor_sync(0xffffffffu, p, 2);
        p += __shfl_xor_sync(0xffffffffu, p, 1);
        if (s == 0) {
            float y = p + Dv * xv;
            float z = zp[(size_t)t * (2 * DI)];
            yp[(size_t)t * DI] = __float2half(y * (z / (1.f + __expf(-z))));
        }
    }
}

// ---------------------------------------------------------------------------
// residual add + LayerNorm (unbiased std, eps added to std)
// ---------------------------------------------------------------------------
__global__ __launch_bounds__(256)
void add_layernorm(const float* __restrict__ res, const float* __restrict__ alpha,
                   const float* __restrict__ beta, float* __restrict__ out)
{
    __shared__ float red[8];
    int row = blockIdx.x;
    int tid = threadIdx.x;

    float loc[4];
    float sgm = 0.f;
#pragma unroll
    for (int j = 0; j < 4; j++) {
        int i = tid + j * 256;
        loc[j] = res[(size_t)row * DM + i] + g_mmout[(size_t)row * DM + i];
        sgm += loc[j];
    }
#pragma unroll
    for (int o = 16; o; o >>= 1) sgm += __shfl_xor_sync(0xffffffffu, sgm, o);
    if ((tid & 31) == 0) red[tid >> 5] = sgm;
    __syncthreads();
    float tot = red[0];
#pragma unroll
    for (int i = 1; i < 8; i++) tot += red[i];
    float mean = tot * (1.f / DM);
    __syncthreads();

    float q = 0.f;
#pragma unroll
    for (int j = 0; j < 4; j++) {
        float df = loc[j] - mean;
        q += df * df;
    }
#pragma unroll
    for (int o = 16; o; o >>= 1) q += __shfl_xor_sync(0xffffffffu, q, o);
    if ((tid & 31) == 0) red[tid >> 5] = q;
    __syncthreads();
    float qt = red[0];
#pragma unroll
    for (int i = 1; i < 8; i++) qt += red[i];

    float stdv = sqrtf(qt * (1.f / (DM - 1)));
    float inv = 1.f / (stdv + 1e-6f);
#pragma unroll
    for (int j = 0; j < 4; j++) {
        int i = tid + j * 256;
        out[(size_t)row * DM + i] = alpha[i] * (loc[j] - mean) * inv + beta[i];
    }
}

// ---------------------------------------------------------------------------
// Launch sequence (gemm1 deliberately placed 4th for the profiler slot)
// ---------------------------------------------------------------------------
extern "C" void kernel_launch(void* const* d_in, const int* in_sizes, int n_in,
                              void* d_out, int out_size)
{
    const float* x      = (const float*)d_in[0];
    const float* W_in   = (const float*)d_in[1];
    const float* b_in   = (const float*)d_in[2];
    const float* conv_w = (const float*)d_in[3];
    const float* conv_b = (const float*)d_in[4];
    const float* W_xp   = (const float*)d_in[5];
    const float* b_xp   = (const float*)d_in[6];
    const float* W_dt   = (const float*)d_in[7];
    const float* b_dt   = (const float*)d_in[8];
    const float* A_log  = (const float*)d_in[9];
    const float* D_skip = (const float*)d_in[10];
    const float* W_out  = (const float*)d_in[11];
    const float* b_out  = (const float*)d_in[12];
    const float* alpha  = (const float*)d_in[13];
    const float* beta   = (const float*)d_in[14];
    float* out = (float*)d_out;

    float *xz, *delta, *mmout;
    __half *xh, *xconvh, *yzh, *wt_in, *wt_dt, *wt_out;
    cudaGetSymbolAddress((void**)&xz,     g_xz);
    cudaGetSymbolAddress((void**)&delta,  g_delta);
    cudaGetSymbolAddress((void**)&mmout,  g_mmout);
    cudaGetSymbolAddress((void**)&xh,     g_xh);
    cudaGetSymbolAddress((void**)&xconvh, g_xconvh);
    cudaGetSymbolAddress((void**)&yzh,    g_yzh);
    cudaGetSymbolAddress((void**)&wt_in,  g_wt_in);
    cudaGetSymbolAddress((void**)&wt_dt,  g_wt_dt);
    cudaGetSymbolAddress((void**)&wt_out, g_wt_out);

    cudaFuncSetAttribute(gemm_mma<0>, cudaFuncAttributeMaxDynamicSharedMemorySize, GSMEM);
    cudaFuncSetAttribute(gemm_mma<1>, cudaFuncAttributeMaxDynamicSharedMemorySize, GSMEM);

    // prep
    to_half<<<(MROWS * DM + 255) / 256, 256>>>(x, xh, MROWS * DM);            // 0
    transposeW<<<dim3((2 * DI) / 32, DM / 32), 256>>>(W_in, wt_in, DM, 2 * DI); // 1
    transposeW<<<dim3(DI / 32, DI / 32),        256>>>(W_dt, wt_dt, DI, DI);  // 2

    // 1) in-proj (launch index 3 — profiler slot)
    gemm_mma<0><<<dim3((2 * DI) / BN, MROWS / BM), 256, GSMEM>>>(
        xh, wt_in, b_in, xz, MROWS, 2 * DI, DM);                              // 3

    // 2) conv + silu
    conv_silu<<<(MROWS * DI) / 256, 256>>>(conv_w, conv_b);                   // 4
    // 3) B,C projection
    proj_bc<<<MROWS / 8, 256>>>(W_xp, b_xp);                                  // 5
    // 4) delta GEMM
    gemm_mma<1><<<dim3(DI / BN, MROWS / BM), 256, GSMEM>>>(
        xconvh, wt_dt, b_dt, delta, MROWS, DI, DI);                           // 6

    // 5) chunked selective scan
    scan_pass1<<<(B_SZ * DI * NCHUNK) / 8, 128>>>(A_log);                     // 7
    scan_combine<<<(B_SZ * DI * DS) / 256, 256>>>(A_log);                     // 8
    scan_pass2<<<(B_SZ * DI * NCHUNK) / 8, 128>>>(A_log, D_skip);             // 9

    // 6) out-proj
    transposeW<<<dim3(DM / 32, DI / 32), 256>>>(W_out, wt_out, DI, DM);       // 10
    gemm_mma<0><<<dim3(DM / BN, MROWS / BM), 256, GSMEM>>>(
        yzh, wt_out, b_out, mmout, MROWS, DM, DI);                            // 11

    // 7) residual + layernorm
    add_layernorm<<<MROWS, 256>>>(x, alpha, beta, out);                       // 12
}

// round 9
// speedup vs baseline: 2.6263x; 1.3984x over previous
#include <cuda_runtime.h>
#include <cuda_fp16.h>
#include <math.h>
#include <stdint.h>

#define B_SZ   2
#define LSEQ   1024
#define DM     1024
#define DI     2048
#define DS     16
#define MROWS  (B_SZ * LSEQ)   // 2048
#define NCHUNK 16
#define CLEN   (LSEQ / NCHUNK) // 64

// ---------------------------------------------------------------------------
// Scratch (__device__ globals; no allocations allowed)
// ---------------------------------------------------------------------------
__device__ float  g_xz[MROWS * 2 * DI];
__device__ float  g_xconv[MROWS * DI];
__device__ float  g_delta[MROWS * DI];
__device__ float  g_bc[MROWS * 2 * DS];
__device__ float  g_mmout[MROWS * DM];
__device__ __half g_xh[MROWS * DM];
__device__ __half g_xconvh[MROWS * DI];
__device__ __half g_yzh[MROWS * DI];
__device__ __half g_wt_in[(2 * DI) * DM];
__device__ __half g_wt_dt[DI * DI];
__device__ __half g_wt_out[DM * DI];
// chunked-scan intermediates
__device__ float  g_E[B_SZ * DI * NCHUNK * DS];
__device__ float  g_S[B_SZ * DI * NCHUNK];
__device__ float  g_Hi[B_SZ * DI * NCHUNK * DS];

// ---------------------------------------------------------------------------
// helpers
// ---------------------------------------------------------------------------
static __device__ __forceinline__ uint32_t smem_u32(const void* p) {
    uint32_t a;
    asm("{ .reg .u64 t; cvta.to.shared.u64 t, %1; cvt.u32.u64 %0, t; }"
        : "=r"(a) : "l"(p));
    return a;
}
static __device__ __forceinline__ void cp_async16(uint32_t sa, const void* ga) {
    asm volatile("cp.async.cg.shared.global [%0], [%1], 16;" :: "r"(sa), "l"(ga));
}
static __device__ __forceinline__ void cp_commit() {
    asm volatile("cp.async.commit_group;" ::: "memory");
}
static __device__ __forceinline__ void cp_wait2() {
    asm volatile("cp.async.wait_group 2;" ::: "memory");
}
static __device__ __forceinline__ float ex2f(float x) {
    float r;
    asm("ex2.approx.f32 %0, %1;" : "=f"(r) : "f"(x));
    return r;
}
static __device__ __forceinline__ void mma16816(float* d, const uint32_t* a,
                                                const uint32_t* b) {
    asm volatile(
        "mma.sync.aligned.m16n8k16.row.col.f32.f16.f16.f32 "
        "{%0,%1,%2,%3}, {%4,%5,%6,%7}, {%8,%9}, {%0,%1,%2,%3};"
        : "+f"(d[0]), "+f"(d[1]), "+f"(d[2]), "+f"(d[3])
        : "r"(a[0]), "r"(a[1]), "r"(a[2]), "r"(a[3]), "r"(b[0]), "r"(b[1]));
}
static __device__ __forceinline__ void ldsm_x4(uint32_t* r, uint32_t addr) {
    asm volatile("ldmatrix.sync.aligned.m8n8.x4.shared.b16 {%0,%1,%2,%3}, [%4];"
                 : "=r"(r[0]), "=r"(r[1]), "=r"(r[2]), "=r"(r[3]) : "r"(addr));
}
static __device__ __forceinline__ void ldsm_x2(uint32_t* r, uint32_t addr) {
    asm volatile("ldmatrix.sync.aligned.m8n8.x2.shared.b16 {%0,%1}, [%2];"
                 : "=r"(r[0]), "=r"(r[1]) : "r"(addr));
}

// ---------------------------------------------------------------------------
// fp16 mma.sync GEMM (fp32 accum), ldmatrix fragment loads.
// EPI=1 -> softplus. 128x128x32 tiles, 4-stage cp.async, 256 threads.
// ---------------------------------------------------------------------------
#define BM 128
#define BN 128
#define BK 32
#define STRDH 40
#define ATILEH (BM * STRDH)
#define BTILEH (BN * STRDH)
#define NSTG 4
#define GSMEM ((ATILEH + BTILEH) * NSTG * 2)   // 81920 bytes

template <int EPI>
__global__ __launch_bounds__(256, 2)
void gemm_mma(const __half* __restrict__ A, const __half* __restrict__ Bt,
              const float* __restrict__ bias, float* __restrict__ C,
              int M, int N, int K)
{
    extern __shared__ __half smh[];
    __half* As = smh;
    __half* Bs = smh + NSTG * ATILEH;

    const int tid  = threadIdx.x;
    const int lane = tid & 31;
    const int wid  = tid >> 5;
    const int wm   = (wid >> 2) * 64;
    const int wn   = (wid & 3) * 32;
    const int bm = blockIdx.y * BM;
    const int bn = blockIdx.x * BN;

    float acc[4][4][4];
#pragma unroll
    for (int mi = 0; mi < 4; mi++)
#pragma unroll
        for (int ni = 0; ni < 4; ni++)
#pragma unroll
            for (int r = 0; r < 4; r++) acc[mi][ni][r] = 0.f;

    auto load_tile = [&](int j) {
        const int stg = j % NSTG;
        const int k0 = j * BK;
        __half* ad = As + stg * ATILEH;
        __half* bd = Bs + stg * BTILEH;
#pragma unroll
        for (int q = 0; q < 2; q++) {
            int ch = tid + q * 256;
            int row = ch >> 2, col = ch & 3;
            cp_async16(smem_u32(ad + row * STRDH + col * 8),
                       A + (size_t)(bm + row) * K + k0 + col * 8);
        }
#pragma unroll
        for (int q = 0; q < 2; q++) {
            int ch = tid + q * 256;
            int row = ch >> 2, col = ch & 3;
            cp_async16(smem_u32(bd + row * STRDH + col * 8),
                       Bt + (size_t)(bn + row) * K + k0 + col * 8);
        }
    };

    const int KT = K / BK;
    load_tile(0); cp_commit();
    load_tile(1); cp_commit();
    load_tile(2); cp_commit();

    for (int i = 0; i < KT; i++) {
        cp_wait2();
        __syncthreads();
        if (i + 3 < KT) load_tile(i + 3);
        cp_commit();

        const int stg = i % NSTG;
        const __half* ad = As + stg * ATILEH;
        const __half* bd = Bs + stg * BTILEH;

#pragma unroll
        for (int kk = 0; kk < BK; kk += 16) {
            uint32_t af[4][4];
            uint32_t bf[4][2];
#pragma unroll
            for (int mi = 0; mi < 4; mi++) {
                uint32_t a_addr = smem_u32(
                    ad + (wm + mi * 16 + (lane & 15)) * STRDH + kk + (lane >> 4) * 8);
                ldsm_x4(af[mi], a_addr);
            }
#pragma unroll
            for (int ni = 0; ni < 4; ni++) {
                uint32_t b_addr = smem_u32(
                    bd + (wn + ni * 8 + (lane & 7)) * STRDH + kk + ((lane >> 3) & 1) * 8);
                ldsm_x2(bf[ni], b_addr);
            }
#pragma unroll
            for (int mi = 0; mi < 4; mi++)
#pragma unroll
                for (int ni = 0; ni < 4; ni++)
                    mma16816(acc[mi][ni], af[mi], bf[ni]);
        }
    }

#pragma unroll
    for (int mi = 0; mi < 4; mi++) {
#pragma unroll
        for (int ni = 0; ni < 4; ni++) {
            int r0 = bm + wm + mi * 16 + (lane >> 2);
            int c0 = bn + wn + ni * 8 + (lane & 3) * 2;
            float2 bv = *(const float2*)(bias + c0);
            float2 v0, v1;
            v0.x = acc[mi][ni][0] + bv.x;
            v0.y = acc[mi][ni][1] + bv.y;
            v1.x = acc[mi][ni][2] + bv.x;
            v1.y = acc[mi][ni][3] + bv.y;
            if (EPI == 1) {
                v0.x = (v0.x > 15.f) ? v0.x : log1pf(__expf(v0.x));
                v0.y = (v0.y > 15.f) ? v0.y : log1pf(__expf(v0.y));
                v1.x = (v1.x > 15.f) ? v1.x : log1pf(__expf(v1.x));
                v1.y = (v1.y > 15.f) ? v1.y : log1pf(__expf(v1.y));
            }
            *(float2*)(C + (size_t)r0 * N + c0) = v0;
            *(float2*)(C + (size_t)(r0 + 8) * N + c0) = v1;
        }
    }
}

// ---------------------------------------------------------------------------
// fp32 -> fp16 copy (for x)
// ---------------------------------------------------------------------------
__global__ __launch_bounds__(256)
void to_half(const float* __restrict__ in, __half* __restrict__ out, int n)
{
    int i = blockIdx.x * 256 + threadIdx.x;
    if (i < n) out[i] = __float2half(in[i]);
}

// ---------------------------------------------------------------------------
// Weight transpose to half: Wt[n,k] = half(W[k,n])
// ---------------------------------------------------------------------------
__global__ __launch_bounds__(256)
void transposeW(const float* __restrict__ W, __half* __restrict__ Wt, int K, int N)
{
    __shared__ float t[32][33];
    int n0 = blockIdx.x * 32, k0 = blockIdx.y * 32;
    int tx = threadIdx.x & 31, ty = threadIdx.x >> 5;
#pragma unroll
    for (int i = ty; i < 32; i += 8)
        t[i][tx] = W[(size_t)(k0 + i) * N + n0 + tx];
    __syncthreads();
#pragma unroll
    for (int i = ty; i < 32; i += 8)
        Wt[(size_t)(n0 + i) * K + k0 + tx] = __float2half(t[tx][i]);
}

// ---------------------------------------------------------------------------
// Depthwise causal conv (width 4) + SiLU; fp32 + half outputs
// ---------------------------------------------------------------------------
__global__ void conv_silu(const float* __restrict__ cw, const float* __restrict__ cb)
{
    int idx = blockIdx.x * 256 + threadIdx.x;
    if (idx >= MROWS * DI) return;
    int d  = idx & (DI - 1);
    int lm = idx >> 11;
    int l  = lm & (LSEQ - 1);

    const float* xp = g_xz + (size_t)lm * (2 * DI) + d;
    float acc = cb[d];
#pragma unroll
    for (int j = 0; j < 4; j++) {
        int ll = l - 3 + j;
        if (ll >= 0) acc += xp[(j - 3) * (2 * DI)] * cw[d * 4 + j];
    }
    float v = acc / (1.f + __expf(-acc));
    g_xconv[idx]  = v;
    g_xconvh[idx] = __float2half(v);
}

// ---------------------------------------------------------------------------
// B,C projection (K=2048, N=32), fp32
// ---------------------------------------------------------------------------
__global__ __launch_bounds__(256)
void proj_bc(const float* __restrict__ W, const float* __restrict__ bias)
{
    __shared__ float Ws[256 * 32];
    int m = blockIdx.x * 8 + (threadIdx.x >> 5);
    int n = threadIdx.x & 31;
    const float* a = g_xconv + (size_t)m * DI;
    float acc = bias[n];
    for (int k0 = 0; k0 < DI; k0 += 256) {
        __syncthreads();
        for (int i = threadIdx.x; i < 256 * 32; i += 256)
            Ws[i] = W[(size_t)k0 * 32 + i];
        __syncthreads();
#pragma unroll 8
        for (int kk = 0; kk < 256; kk++)
            acc += a[k0 + kk] * Ws[kk * 32 + n];
    }
    g_bc[(size_t)m * 32 + n] = acc;
}

// ---------------------------------------------------------------------------
// Chunked scan, d-parallel: 1 lane = 1 channel d carrying all 16 states.
// All global loads coalesced (lanes span 32 consecutive d).
// Pass 1: h-scan from 0 per chunk + sum(delta).
// ---------------------------------------------------------------------------
#define LOG2E 1.44269504088896f

__global__ __launch_bounds__(128)
void scan_pass1(const float* __restrict__ A_log)
{
    int chunk = blockIdx.x & (NCHUNK - 1);
    int bdg   = blockIdx.x >> 4;            // 0..31
    int bd    = bdg * 128 + threadIdx.x;
    int b     = bd >> 11;
    int d     = bd & (DI - 1);

    __shared__ float bcs[CLEN][DS];         // B only (4KB)
    const float* bcp = g_bc + ((size_t)b * LSEQ + chunk * CLEN) * (2 * DS);
    for (int i = threadIdx.x; i < CLEN * DS; i += 128) {
        int t = i >> 4, s = i & 15;
        bcs[t][s] = bcp[t * 32 + s];
    }
    __syncthreads();

    float Av[DS];
#pragma unroll
    for (int s = 0; s < DS; s++)
        Av[s] = -__expf(A_log[d * DS + s]) * LOG2E;

    float h[DS];
#pragma unroll
    for (int s = 0; s < DS; s++) h[s] = 0.f;
    float S = 0.f;

    const size_t base = ((size_t)b * LSEQ + chunk * CLEN) * DI + d;
    const float* dp = g_delta + base;
    const float* xp = g_xconv + base;

    for (int t = 0; t < CLEN; t++) {
        float dv = dp[(size_t)t * DI];
        float xv = xp[(size_t)t * DI];
        float u = dv * xv;
        S += dv;
#pragma unroll
        for (int s = 0; s < DS; s++)
            h[s] = fmaf(ex2f(dv * Av[s]), h[s], u * bcs[t][s]);
    }

    int gid = bd * NCHUNK + chunk;
#pragma unroll
    for (int s = 0; s < DS; s++) g_E[gid * DS + s] = h[s];
    g_S[gid] = S;
}

// Combine: per (b,d,s): serial prefix over 16 chunks -> true initial states.
__global__ __launch_bounds__(256)
void scan_combine(const float* __restrict__ A_log)
{
    int idx = blockIdx.x * 256 + threadIdx.x;   // (bd, s)
    int s  = idx & 15;
    int bd = idx >> 4;
    int d  = bd & (DI - 1);
    float Av = -__expf(A_log[d * DS + s]);
    float H = 0.f;
#pragma unroll
    for (int c = 0; c < NCHUNK; c++) {
        int gid = bd * NCHUNK + c;
        g_Hi[gid * DS + s] = H;
        H = fmaf(__expf(Av * g_S[gid]), H, g_E[gid * DS + s]);
    }
}

// Pass 2: re-scan from true init; per-lane C-contraction; emit y*silu(z) half.
__global__ __launch_bounds__(128)
void scan_pass2(const float* __restrict__ A_log, const float* __restrict__ D_skip)
{
    int chunk = blockIdx.x & (NCHUNK - 1);
    int bdg   = blockIdx.x >> 4;
    int bd    = bdg * 128 + threadIdx.x;
    int b     = bd >> 11;
    int d     = bd & (DI - 1);

    __shared__ float bcs[CLEN][2 * DS];     // B and C (8KB)
    const float* bcp = g_bc + ((size_t)b * LSEQ + chunk * CLEN) * (2 * DS);
    for (int i = threadIdx.x; i < CLEN * 2 * DS; i += 128)
        ((float*)bcs)[i] = bcp[i];
    __syncthreads();

    float Av[DS];
#pragma unroll
    for (int s = 0; s < DS; s++)
        Av[s] = -__expf(A_log[d * DS + s]) * LOG2E;
    float Dv = D_skip[d];

    int gid = bd * NCHUNK + chunk;
    float h[DS];
#pragma unroll
    for (int s = 0; s < DS; s++) h[s] = g_Hi[gid * DS + s];

    const size_t base = ((size_t)b * LSEQ + chunk * CLEN) * DI + d;
    const float* dp = g_delta + base;
    const float* xp = g_xconv + base;
    const float* zp = g_xz + ((size_t)b * LSEQ + chunk * CLEN) * (2 * DI) + DI + d;
    __half* yp = g_yzh + base;

    for (int t = 0; t < CLEN; t++) {
        float dv = dp[(size_t)t * DI];
        float xv = xp[(size_t)t * DI];
        float z  = zp[(size_t)t * (2 * DI)];
        float u = dv * xv;
        float y = Dv * xv;
#pragma unroll
        for (int s = 0; s < DS; s++) {
            h[s] = fmaf(ex2f(dv * Av[s]), h[s], u * bcs[t][s]);
            y = fmaf(h[s], bcs[t][DS + s], y);
        }
        yp[(size_t)t * DI] = __float2half(y * (z / (1.f + __expf(-z))));
    }
}

// ---------------------------------------------------------------------------
// residual add + LayerNorm (unbiased std, eps added to std)
// ---------------------------------------------------------------------------
__global__ __launch_bounds__(256)
void add_layernorm(const float* __restrict__ res, const float* __restrict__ alpha,
                   const float* __restrict__ beta, float* __restrict__ out)
{
    __shared__ float red[8];
    int row = blockIdx.x;
    int tid = threadIdx.x;

    float loc[4];
    float sgm = 0.f;
#pragma unroll
    for (int j = 0; j < 4; j++) {
        int i = tid + j * 256;
        loc[j] = res[(size_t)row * DM + i] + g_mmout[(size_t)row * DM + i];
        sgm += loc[j];
    }
#pragma unroll
    for (int o = 16; o; o >>= 1) sgm += __shfl_xor_sync(0xffffffffu, sgm, o);
    if ((tid & 31) == 0) red[tid >> 5] = sgm;
    __syncthreads();
    float tot = red[0];
#pragma unroll
    for (int i = 1; i < 8; i++) tot += red[i];
    float mean = tot * (1.f / DM);
    __syncthreads();

    float q = 0.f;
#pragma unroll
    for (int j = 0; j < 4; j++) {
        float df = loc[j] - mean;
        q += df * df;
    }
#pragma unroll
    for (int o = 16; o; o >>= 1) q += __shfl_xor_sync(0xffffffffu, q, o);
    if ((tid & 31) == 0) red[tid >> 5] = q;
    __syncthreads();
    float qt = red[0];
#pragma unroll
    for (int i = 1; i < 8; i++) qt += red[i];

    float stdv = sqrtf(qt * (1.f / (DM - 1)));
    float inv = 1.f / (stdv + 1e-6f);
#pragma unroll
    for (int j = 0; j < 4; j++) {
        int i = tid + j * 256;
        out[(size_t)row * DM + i] = alpha[i] * (loc[j] - mean) * inv + beta[i];
    }
}

// ---------------------------------------------------------------------------
// Launch sequence (gemm1 at launch index 3 = profiler slot)
// ---------------------------------------------------------------------------
extern "C" void kernel_launch(void* const* d_in, const int* in_sizes, int n_in,
                              void* d_out, int out_size)
{
    const float* x      = (const float*)d_in[0];
    const float* W_in   = (const float*)d_in[1];
    const float* b_in   = (const float*)d_in[2];
    const float* conv_w = (const float*)d_in[3];
    const float* conv_b = (const float*)d_in[4];
    const float* W_xp   = (const float*)d_in[5];
    const float* b_xp   = (const float*)d_in[6];
    const float* W_dt   = (const float*)d_in[7];
    const float* b_dt   = (const float*)d_in[8];
    const float* A_log  = (const float*)d_in[9];
    const float* D_skip = (const float*)d_in[10];
    const float* W_out  = (const float*)d_in[11];
    const float* b_out  = (const float*)d_in[12];
    const float* alpha  = (const float*)d_in[13];
    const float* beta   = (const float*)d_in[14];
    float* out = (float*)d_out;

    float *xz, *delta, *mmout;
    __half *xh, *xconvh, *yzh, *wt_in, *wt_dt, *wt_out;
    cudaGetSymbolAddress((void**)&xz,     g_xz);
    cudaGetSymbolAddress((void**)&delta,  g_delta);
    cudaGetSymbolAddress((void**)&mmout,  g_mmout);
    cudaGetSymbolAddress((void**)&xh,     g_xh);
    cudaGetSymbolAddress((void**)&xconvh, g_xconvh);
    cudaGetSymbolAddress((void**)&yzh,    g_yzh);
    cudaGetSymbolAddress((void**)&wt_in,  g_wt_in);
    cudaGetSymbolAddress((void**)&wt_dt,  g_wt_dt);
    cudaGetSymbolAddress((void**)&wt_out, g_wt_out);

    cudaFuncSetAttribute(gemm_mma<0>, cudaFuncAttributeMaxDynamicSharedMemorySize, GSMEM);
    cudaFuncSetAttribute(gemm_mma<1>, cudaFuncAttributeMaxDynamicSharedMemorySize, GSMEM);

    // prep
    to_half<<<(MROWS * DM + 255) / 256, 256>>>(x, xh, MROWS * DM);              // 0
    transposeW<<<dim3((2 * DI) / 32, DM / 32), 256>>>(W_in, wt_in, DM, 2 * DI); // 1
    transposeW<<<dim3(DI / 32, DI / 32),        256>>>(W_dt, wt_dt, DI, DI);    // 2

    // 1) in-proj (profiler slot)
    gemm_mma<0><<<dim3((2 * DI) / BN, MROWS / BM), 256, GSMEM>>>(
        xh, wt_in, b_in, xz, MROWS, 2 * DI, DM);                                // 3

    // 2) conv + silu
    conv_silu<<<(MROWS * DI) / 256, 256>>>(conv_w, conv_b);                     // 4
    // 3) B,C projection
    proj_bc<<<MROWS / 8, 256>>>(W_xp, b_xp);                                    // 5
    // 4) delta GEMM
    gemm_mma<1><<<dim3(DI / BN, MROWS / BM), 256, GSMEM>>>(
        xconvh, wt_dt, b_dt, delta, MROWS, DI, DI);                             // 6

    // 5) chunked selective scan (d-parallel)
    scan_pass1<<<(B_SZ * DI / 128) * NCHUNK, 128>>>(A_log);                     // 7
    scan_combine<<<(B_SZ * DI * DS) / 256, 256>>>(A_log);                       // 8
    scan_pass2<<<(B_SZ * DI / 128) * NCHUNK, 128>>>(A_log, D_skip);             // 9

    // 6) out-proj
    transposeW<<<dim3(DM / 32, DI / 32), 256>>>(W_out, wt_out, DI, DM);         // 10
    gemm_mma<0><<<dim3(DM / BN, MROWS / BM), 256, GSMEM>>>(
        yzh, wt_out, b_out, mmout, MROWS, DM, DI);                              // 11

    // 7) residual + layernorm
    add_layernorm<<<MROWS, 256>>>(x, alpha, beta, out);                         // 12
}

// round 10
// speedup vs baseline: 3.2994x; 1.2563x over previous
#include <cuda_runtime.h>
#include <cuda_fp16.h>
#include <math.h>
#include <stdint.h>

#define B_SZ   2
#define LSEQ   1024
#define DM     1024
#define DI     2048
#define DS     16
#define MROWS  (B_SZ * LSEQ)   // 2048
#define NCHUNK 16
#define CLEN   (LSEQ / NCHUNK) // 64
#define NDBC   2176            // 2048 delta + 32 B/C + 96 pad (17 * 128)

// ---------------------------------------------------------------------------
// Scratch (__device__ globals; zero-initialized at load -> padding rows stay 0)
// ---------------------------------------------------------------------------
__device__ float  g_xz[MROWS * 2 * DI];
__device__ float  g_xconv[MROWS * DI];
__device__ float  g_dbc[MROWS * NDBC];       // [delta(2048) | B(16) C(16) | pad]
__device__ float  g_mmout[MROWS * DM];
__device__ __half g_xh[MROWS * DM];
__device__ __half g_xconvh[MROWS * DI];
__device__ __half g_yzh[MROWS * DI];
__device__ __half g_wt_in[(2 * DI) * DM];
__device__ __half g_wt_dtx[NDBC * DI];       // W_dt^T rows 0..2047, W_xp^T rows 2048..2079, zeros above
__device__ __half g_wt_out[DM * DI];
// chunked-scan intermediates
__device__ float  g_E[B_SZ * DI * NCHUNK * DS];
__device__ float  g_S[B_SZ * DI * NCHUNK];
__device__ float  g_Hi[B_SZ * DI * NCHUNK * DS];

// ---------------------------------------------------------------------------
// helpers
// ---------------------------------------------------------------------------
static __device__ __forceinline__ uint32_t smem_u32(const void* p) {
    uint32_t a;
    asm("{ .reg .u64 t; cvta.to.shared.u64 t, %1; cvt.u32.u64 %0, t; }"
        : "=r"(a) : "l"(p));
    return a;
}
static __device__ __forceinline__ void cp_async16(uint32_t sa, const void* ga) {
    asm volatile("cp.async.cg.shared.global [%0], [%1], 16;" :: "r"(sa), "l"(ga));
}
static __device__ __forceinline__ void cp_commit() {
    asm volatile("cp.async.commit_group;" ::: "memory");
}
static __device__ __forceinline__ void cp_wait2() {
    asm volatile("cp.async.wait_group 2;" ::: "memory");
}
static __device__ __forceinline__ float ex2f(float x) {
    float r;
    asm("ex2.approx.f32 %0, %1;" : "=f"(r) : "f"(x));
    return r;
}
static __device__ __forceinline__ void mma16816(float* d, const uint32_t* a,
                                                const uint32_t* b) {
    asm volatile(
        "mma.sync.aligned.m16n8k16.row.col.f32.f16.f16.f32 "
        "{%0,%1,%2,%3}, {%4,%5,%6,%7}, {%8,%9}, {%0,%1,%2,%3};"
        : "+f"(d[0]), "+f"(d[1]), "+f"(d[2]), "+f"(d[3])
        : "r"(a[0]), "r"(a[1]), "r"(a[2]), "r"(a[3]), "r"(b[0]), "r"(b[1]));
}
static __device__ __forceinline__ void ldsm_x4(uint32_t* r, uint32_t addr) {
    asm volatile("ldmatrix.sync.aligned.m8n8.x4.shared.b16 {%0,%1,%2,%3}, [%4];"
                 : "=r"(r[0]), "=r"(r[1]), "=r"(r[2]), "=r"(r[3]) : "r"(addr));
}
static __device__ __forceinline__ void ldsm_x2(uint32_t* r, uint32_t addr) {
    asm volatile("ldmatrix.sync.aligned.m8n8.x2.shared.b16 {%0,%1}, [%2];"
                 : "=r"(r[0]), "=r"(r[1]) : "r"(addr));
}

// ---------------------------------------------------------------------------
// fp16 mma.sync GEMM (fp32 accum), templated tiles.
// EPI: 0 = bias only; 1 = bias+softplus; 2 = combined delta/BC epilogue
//      (softplus + bias for col<DI, bias2 for DI<=col<DI+32, raw above).
// ---------------------------------------------------------------------------
#define BK 32
#define STRDH 40
#define NSTG 4

template <int TBM, int TBN, int TWM, int TWN, int EPI>
__global__ __launch_bounds__(256, 2)
void gemm_mma(const __half* __restrict__ A, const __half* __restrict__ Bt,
              const float* __restrict__ bias, const float* __restrict__ bias2,
              float* __restrict__ C, int M, int N, int K)
{
    constexpr int ATILE = TBM * STRDH;
    constexpr int BTILE = TBN * STRDH;
    constexpr int NWN = TBN / TWN;          // warps along n
    constexpr int MI = TWM / 16;
    constexpr int NI = TWN / 8;

    extern __shared__ __half smh[];
    __half* As = smh;
    __half* Bs = smh + NSTG * ATILE;

    const int tid  = threadIdx.x;
    const int lane = tid & 31;
    const int wid  = tid >> 5;
    const int wm   = (wid / NWN) * TWM;
    const int wn   = (wid % NWN) * TWN;
    const int bm = blockIdx.y * TBM;
    const int bn = blockIdx.x * TBN;

    float acc[MI][NI][4];
#pragma unroll
    for (int mi = 0; mi < MI; mi++)
#pragma unroll
        for (int ni = 0; ni < NI; ni++)
#pragma unroll
            for (int r = 0; r < 4; r++) acc[mi][ni][r] = 0.f;

    auto load_tile = [&](int j) {
        const int stg = j % NSTG;
        const int k0 = j * BK;
        __half* ad = As + stg * ATILE;
        __half* bd = Bs + stg * BTILE;
#pragma unroll
        for (int q = 0; q < TBM / 64; q++) {
            int ch = tid + q * 256;
            int row = ch >> 2, col = ch & 3;
            cp_async16(smem_u32(ad + row * STRDH + col * 8),
                       A + (size_t)(bm + row) * K + k0 + col * 8);
        }
#pragma unroll
        for (int q = 0; q < TBN / 64; q++) {
            int ch = tid + q * 256;
            int row = ch >> 2, col = ch & 3;
            cp_async16(smem_u32(bd + row * STRDH + col * 8),
                       Bt + (size_t)(bn + row) * K + k0 + col * 8);
        }
    };

    const int KT = K / BK;
    load_tile(0); cp_commit();
    load_tile(1); cp_commit();
    load_tile(2); cp_commit();

    for (int i = 0; i < KT; i++) {
        cp_wait2();
        __syncthreads();
        if (i + 3 < KT) load_tile(i + 3);
        cp_commit();

        const int stg = i % NSTG;
        const __half* ad = As + stg * ATILE;
        const __half* bd = Bs + stg * BTILE;

#pragma unroll
        for (int kk = 0; kk < BK; kk += 16) {
            uint32_t af[MI][4];
            uint32_t bf[NI][2];
#pragma unroll
            for (int mi = 0; mi < MI; mi++) {
                uint32_t a_addr = smem_u32(
                    ad + (wm + mi * 16 + (lane & 15)) * STRDH + kk + (lane >> 4) * 8);
                ldsm_x4(af[mi], a_addr);
            }
#pragma unroll
            for (int ni = 0; ni < NI; ni++) {
                uint32_t b_addr = smem_u32(
                    bd + (wn + ni * 8 + (lane & 7)) * STRDH + kk + ((lane >> 3) & 1) * 8);
                ldsm_x2(bf[ni], b_addr);
            }
#pragma unroll
            for (int mi = 0; mi < MI; mi++)
#pragma unroll
                for (int ni = 0; ni < NI; ni++)
                    mma16816(acc[mi][ni], af[mi], bf[ni]);
        }
    }

    // ---- epilogue ---------------------------------------------------------
#pragma unroll
    for (int mi = 0; mi < MI; mi++) {
#pragma unroll
        for (int ni = 0; ni < NI; ni++) {
            int r0 = bm + wm + mi * 16 + (lane >> 2);
            int c0 = bn + wn + ni * 8 + (lane & 3) * 2;
            float2 bv;
            bool sp;
            if (EPI == 2) {
                if (c0 < DI)            { bv = *(const float2*)(bias + c0);       sp = true;  }
                else if (c0 < DI + 32)  { bv = *(const float2*)(bias2 + c0 - DI); sp = false; }
                else                    { bv = make_float2(0.f, 0.f);             sp = false; }
            } else {
                bv = *(const float2*)(bias + c0);
                sp = (EPI == 1);
            }
            float2 v0, v1;
            v0.x = acc[mi][ni][0] + bv.x;
            v0.y = acc[mi][ni][1] + bv.y;
            v1.x = acc[mi][ni][2] + bv.x;
            v1.y = acc[mi][ni][3] + bv.y;
            if (sp) {
                v0.x = (v0.x > 15.f) ? v0.x : log1pf(__expf(v0.x));
                v0.y = (v0.y > 15.f) ? v0.y : log1pf(__expf(v0.y));
                v1.x = (v1.x > 15.f) ? v1.x : log1pf(__expf(v1.x));
                v1.y = (v1.y > 15.f) ? v1.y : log1pf(__expf(v1.y));
            }
            *(float2*)(C + (size_t)r0 * N + c0) = v0;
            *(float2*)(C + (size_t)(r0 + 8) * N + c0) = v1;
        }
    }
}

// main config (gemm1, gemm2)
#define GSMEM_128 ((128 + 128) * STRDH * 2 * NSTG)   // 81920
// gemm3 config
#define GSMEM_64  ((128 + 64) * STRDH * 2 * NSTG)    // 61440

// ---------------------------------------------------------------------------
// fp32 -> fp16 copy
// ---------------------------------------------------------------------------
__global__ __launch_bounds__(256)
void to_half(const float* __restrict__ in, __half* __restrict__ out, int n)
{
    int i = blockIdx.x * 256 + threadIdx.x;
    if (i < n) out[i] = __float2half(in[i]);
}

// ---------------------------------------------------------------------------
// Weight transpose to half: Wt[n,k] = half(W[k,n])
// ---------------------------------------------------------------------------
__global__ __launch_bounds__(256)
void transposeW(const float* __restrict__ W, __half* __restrict__ Wt, int K, int N)
{
    __shared__ float t[32][33];
    int n0 = blockIdx.x * 32, k0 = blockIdx.y * 32;
    int tx = threadIdx.x & 31, ty = threadIdx.x >> 5;
#pragma unroll
    for (int i = ty; i < 32; i += 8)
        t[i][tx] = W[(size_t)(k0 + i) * N + n0 + tx];
    __syncthreads();
#pragma unroll
    for (int i = ty; i < 32; i += 8)
        Wt[(size_t)(n0 + i) * K + k0 + tx] = __float2half(t[tx][i]);
}

// ---------------------------------------------------------------------------
// Depthwise causal conv (width 4) + SiLU; fp32 + half outputs
// ---------------------------------------------------------------------------
__global__ void conv_silu(const float* __restrict__ cw, const float* __restrict__ cb)
{
    int idx = blockIdx.x * 256 + threadIdx.x;
    if (idx >= MROWS * DI) return;
    int d  = idx & (DI - 1);
    int lm = idx >> 11;
    int l  = lm & (LSEQ - 1);

    const float* xp = g_xz + (size_t)lm * (2 * DI) + d;
    float acc = cb[d];
#pragma unroll
    for (int j = 0; j < 4; j++) {
        int ll = l - 3 + j;
        if (ll >= 0) acc += xp[(j - 3) * (2 * DI)] * cw[d * 4 + j];
    }
    float v = acc / (1.f + __expf(-acc));
    g_xconv[idx]  = v;
    g_xconvh[idx] = __float2half(v);
}

// ---------------------------------------------------------------------------
// Chunked scan, d-parallel. delta/B/C all live in g_dbc rows of width NDBC.
// ---------------------------------------------------------------------------
#define LOG2E 1.44269504088896f

__global__ __launch_bounds__(128)
void scan_pass1(const float* __restrict__ A_log)
{
    int chunk = blockIdx.x & (NCHUNK - 1);
    int bdg   = blockIdx.x >> 4;
    int bd    = bdg * 128 + threadIdx.x;
    int b     = bd >> 11;
    int d     = bd & (DI - 1);

    __shared__ float bcs[CLEN][DS];
    const float* bcp = g_dbc + ((size_t)b * LSEQ + chunk * CLEN) * NDBC + DI;
    for (int i = threadIdx.x; i < CLEN * DS; i += 128) {
        int t = i >> 4, s = i & 15;
        bcs[t][s] = bcp[(size_t)t * NDBC + s];
    }
    __syncthreads();

    float Av[DS];
#pragma unroll
    for (int s = 0; s < DS; s++)
        Av[s] = -__expf(A_log[d * DS + s]) * LOG2E;

    float h[DS];
#pragma unroll
    for (int s = 0; s < DS; s++) h[s] = 0.f;
    float S = 0.f;

    const float* dp = g_dbc + ((size_t)b * LSEQ + chunk * CLEN) * NDBC + d;
    const float* xp = g_xconv + ((size_t)b * LSEQ + chunk * CLEN) * DI + d;

    for (int t = 0; t < CLEN; t++) {
        float dv = dp[(size_t)t * NDBC];
        float xv = xp[(size_t)t * DI];
        float u = dv * xv;
        S += dv;
#pragma unroll
        for (int s = 0; s < DS; s++)
            h[s] = fmaf(ex2f(dv * Av[s]), h[s], u * bcs[t][s]);
    }

    int gid = bd * NCHUNK + chunk;
#pragma unroll
    for (int s = 0; s < DS; s++) g_E[gid * DS + s] = h[s];
    g_S[gid] = S;
}

__global__ __launch_bounds__(256)
void scan_combine(const float* __restrict__ A_log)
{
    int idx = blockIdx.x * 256 + threadIdx.x;
    int s  = idx & 15;
    int bd = idx >> 4;
    int d  = bd & (DI - 1);
    float Av = -__expf(A_log[d * DS + s]);
    float H = 0.f;
#pragma unroll
    for (int c = 0; c < NCHUNK; c++) {
        int gid = bd * NCHUNK + c;
        g_Hi[gid * DS + s] = H;
        H = fmaf(__expf(Av * g_S[gid]), H, g_E[gid * DS + s]);
    }
}

__global__ __launch_bounds__(128)
void scan_pass2(const float* __restrict__ A_log, const float* __restrict__ D_skip)
{
    int chunk = blockIdx.x & (NCHUNK - 1);
    int bdg   = blockIdx.x >> 4;
    int bd    = bdg * 128 + threadIdx.x;
    int b     = bd >> 11;
    int d     = bd & (DI - 1);

    __shared__ float bcs[CLEN][2 * DS];
    const float* bcp = g_dbc + ((size_t)b * LSEQ + chunk * CLEN) * NDBC + DI;
    for (int i = threadIdx.x; i < CLEN * 2 * DS; i += 128) {
        int t = i >> 5, j = i & 31;
        bcs[t][j] = bcp[(size_t)t * NDBC + j];
    }
    __syncthreads();

    float Av[DS];
#pragma unroll
    for (int s = 0; s < DS; s++)
        Av[s] = -__expf(A_log[d * DS + s]) * LOG2E;
    float Dv = D_skip[d];

    int gid = bd * NCHUNK + chunk;
    float h[DS];
#pragma unroll
    for (int s = 0; s < DS; s++) h[s] = g_Hi[gid * DS + s];

    const float* dp = g_dbc + ((size_t)b * LSEQ + chunk * CLEN) * NDBC + d;
    const float* xp = g_xconv + ((size_t)b * LSEQ + chunk * CLEN) * DI + d;
    const float* zp = g_xz + ((size_t)b * LSEQ + chunk * CLEN) * (2 * DI) + DI + d;
    __half* yp = g_yzh + ((size_t)b * LSEQ + chunk * CLEN) * DI + d;

    for (int t = 0; t < CLEN; t++) {
        float dv = dp[(size_t)t * NDBC];
        float xv = xp[(size_t)t * DI];
        float z  = zp[(size_t)t * (2 * DI)];
        float u = dv * xv;
        float y = Dv * xv;
#pragma unroll
        for (int s = 0; s < DS; s++) {
            h[s] = fmaf(ex2f(dv * Av[s]), h[s], u * bcs[t][s]);
            y = fmaf(h[s], bcs[t][DS + s], y);
        }
        yp[(size_t)t * DI] = __float2half(y * (z / (1.f + __expf(-z))));
    }
}

// ---------------------------------------------------------------------------
// residual add + LayerNorm (unbiased std, eps added to std)
// ---------------------------------------------------------------------------
__global__ __launch_bounds__(256)
void add_layernorm(const float* __restrict__ res, const float* __restrict__ alpha,
                   const float* __restrict__ beta, float* __restrict__ out)
{
    __shared__ float red[8];
    int row = blockIdx.x;
    int tid = threadIdx.x;

    float loc[4];
    float sgm = 0.f;
#pragma unroll
    for (int j = 0; j < 4; j++) {
        int i = tid + j * 256;
        loc[j] = res[(size_t)row * DM + i] + g_mmout[(size_t)row * DM + i];
        sgm += loc[j];
    }
#pragma unroll
    for (int o = 16; o; o >>= 1) sgm += __shfl_xor_sync(0xffffffffu, sgm, o);
    if ((tid & 31) == 0) red[tid >> 5] = sgm;
    __syncthreads();
    float tot = red[0];
#pragma unroll
    for (int i = 1; i < 8; i++) tot += red[i];
    float mean = tot * (1.f / DM);
    __syncthreads();

    float q = 0.f;
#pragma unroll
    for (int j = 0; j < 4; j++) {
        float df = loc[j] - mean;
        q += df * df;
    }
#pragma unroll
    for (int o = 16; o; o >>= 1) q += __shfl_xor_sync(0xffffffffu, q, o);
    if ((tid & 31) == 0) red[tid >> 5] = q;
    __syncthreads();
    float qt = red[0];
#pragma unroll
    for (int i = 1; i < 8; i++) qt += red[i];

    float stdv = sqrtf(qt * (1.f / (DM - 1)));
    float inv = 1.f / (stdv + 1e-6f);
#pragma unroll
    for (int j = 0; j < 4; j++) {
        int i = tid + j * 256;
        out[(size_t)row * DM + i] = alpha[i] * (loc[j] - mean) * inv + beta[i];
    }
}

// ---------------------------------------------------------------------------
// Launch sequence (gemm1 at launch index 3 = profiler slot)
// ---------------------------------------------------------------------------
extern "C" void kernel_launch(void* const* d_in, const int* in_sizes, int n_in,
                              void* d_out, int out_size)
{
    const float* x      = (const float*)d_in[0];
    const float* W_in   = (const float*)d_in[1];
    const float* b_in   = (const float*)d_in[2];
    const float* conv_w = (const float*)d_in[3];
    const float* conv_b = (const float*)d_in[4];
    const float* W_xp   = (const float*)d_in[5];
    const float* b_xp   = (const float*)d_in[6];
    const float* W_dt   = (const float*)d_in[7];
    const float* b_dt   = (const float*)d_in[8];
    const float* A_log  = (const float*)d_in[9];
    const float* D_skip = (const float*)d_in[10];
    const float* W_out  = (const float*)d_in[11];
    const float* b_out  = (const float*)d_in[12];
    const float* alpha  = (const float*)d_in[13];
    const float* beta   = (const float*)d_in[14];
    float* out = (float*)d_out;

    float *xz, *dbc, *mmout;
    __half *xh, *xconvh, *yzh, *wt_in, *wt_dtx, *wt_out;
    cudaGetSymbolAddress((void**)&xz,     g_xz);
    cudaGetSymbolAddress((void**)&dbc,    g_dbc);
    cudaGetSymbolAddress((void**)&mmout,  g_mmout);
    cudaGetSymbolAddress((void**)&xh,     g_xh);
    cudaGetSymbolAddress((void**)&xconvh, g_xconvh);
    cudaGetSymbolAddress((void**)&yzh,    g_yzh);
    cudaGetSymbolAddress((void**)&wt_in,  g_wt_in);
    cudaGetSymbolAddress((void**)&wt_dtx, g_wt_dtx);
    cudaGetSymbolAddress((void**)&wt_out, g_wt_out);

    cudaFuncSetAttribute((const void*)gemm_mma<128,128,64,32,0>,
                         cudaFuncAttributeMaxDynamicSharedMemorySize, GSMEM_128);
    cudaFuncSetAttribute((const void*)gemm_mma<128,128,64,32,2>,
                         cudaFuncAttributeMaxDynamicSharedMemorySize, GSMEM_128);
    cudaFuncSetAttribute((const void*)gemm_mma<128,64,32,32,0>,
                         cudaFuncAttributeMaxDynamicSharedMemorySize, GSMEM_64);

    // prep
    to_half<<<(MROWS * DM + 255) / 256, 256>>>(x, xh, MROWS * DM);              // 0
    transposeW<<<dim3((2 * DI) / 32, DM / 32), 256>>>(W_in, wt_in, DM, 2 * DI); // 1
    transposeW<<<dim3(DI / 32, DI / 32), 256>>>(W_dt, wt_dtx, DI, DI);          // 2

    // 1) in-proj (profiler slot, launch index 3)
    gemm_mma<128,128,64,32,0><<<dim3((2 * DI) / 128, MROWS / 128), 256, GSMEM_128>>>(
        xh, wt_in, b_in, nullptr, xz, MROWS, 2 * DI, DM);                       // 3

    // W_xp^T into rows 2048..2079 of combined weight; W_out^T
    transposeW<<<dim3(1, DI / 32), 256>>>(W_xp, wt_dtx + (size_t)DI * DI, DI, 32); // 4
    transposeW<<<dim3(DM / 32, DI / 32), 256>>>(W_out, wt_out, DI, DM);         // 5

    // 2) conv + silu
    conv_silu<<<(MROWS * DI) / 256, 256>>>(conv_w, conv_b);                     // 6

    // 3+4) combined delta/B/C GEMM: [M,2176] = xconv @ [Wdt | Wxp | 0]
    gemm_mma<128,128,64,32,2><<<dim3(NDBC / 128, MROWS / 128), 256, GSMEM_128>>>(
        xconvh, wt_dtx, b_dt, b_xp, dbc, MROWS, NDBC, DI);                      // 7

    // 5) chunked selective scan (d-parallel)
    scan_pass1<<<(B_SZ * DI / 128) * NCHUNK, 128>>>(A_log);                     // 8
    scan_combine<<<(B_SZ * DI * DS) / 256, 256>>>(A_log);                       // 9
    scan_pass2<<<(B_SZ * DI / 128) * NCHUNK, 128>>>(A_log, D_skip);             // 10

    // 6) out-proj (128x64 tiles -> 256 CTAs)
    gemm_mma<128,64,32,32,0><<<dim3(DM / 64, MROWS / 128), 256, GSMEM_64>>>(
        yzh, wt_out, b_out, nullptr, mmout, MROWS, DM, DI);                     // 11

    // 7) residual + layernorm
    add_layernorm<<<MROWS, 256>>>(x, alpha, beta, out);                         // 12
}